// round 13
// baseline (speedup 1.0000x reference)
#include <cuda_runtime.h>
#include <cuda_bf16.h>
#include <cstdint>

#define NODES 16384
#define BATCH 32
#define F 64

typedef unsigned long long ull;

// Y_k for k=3..14 (level k starts at row YOFF(k); k<3 unused).
__device__ float g_Y[(size_t)16383 * BATCH * F];

__host__ __device__ constexpr size_t YOFF(int k) {   // k >= 1
    return (size_t)(16384 - (16384 >> (k - 1)));
}

#define SW128(x) ((x) ^ (((x) >> 3) & 0x70))

// ---- final kernel dynamic smem (bytes) ----
// B images: W0,W1,W2 hi+lo
#define FB0HI 0
#define FB0LO 8192
#define FB1HI 16384
#define FB1LO 24576
#define FB2HI 32768
#define FB2LO 40960
// stage region: warps 0-6 have 8704B each (2 A-segs of 4352, overlaying their
// 32 out-rows at pitch 272B); warp 7 (gather) region = 4352B (16 G3 rows).
#define FSTG  49152
#define SMF_TOTAL (FSTG + 7 * 8704 + 4352)   // 114432
#define P 68                                  // stage pitch in floats

// ---- Y kernel dynamic smem ----
#define YB_HI 0
#define YB_LO 8192
#define YSTG  16384
#define SMY_TOTAL (YSTG + 8 * 8704)          // 86016

#define FGRID 296
#define YGRID_HMMA 256
#define YGRID_SMALL 32
#define YGRID (YGRID_HMMA + YGRID_SMALL)

// ---------------- helpers ----------------
__device__ __forceinline__ uint32_t smem_u32(const void* p) {
    uint32_t a;
    asm("{ .reg .u64 t; cvta.to.shared.u64 t, %1; cvt.u32.u64 %0, t; }" : "=r"(a) : "l"(p));
    return a;
}
// pack: low half = lo, high half = hi
__device__ __forceinline__ uint32_t cvt2(float lo, float hi) {
    uint32_t r; asm("cvt.rn.bf16x2.f32 %0, %1, %2;" : "=r"(r) : "f"(hi), "f"(lo)); return r;
}
__device__ __forceinline__ float lo16f(uint32_t u) { return __uint_as_float(u << 16); }
__device__ __forceinline__ float hi16f(uint32_t u) { return __uint_as_float(u & 0xffff0000u); }

__device__ __forceinline__ void ldsm4(uint32_t a, uint32_t& r0, uint32_t& r1,
                                      uint32_t& r2, uint32_t& r3) {
    asm volatile("ldmatrix.sync.aligned.m8n8.x4.shared.b16 {%0,%1,%2,%3}, [%4];"
                 : "=r"(r0), "=r"(r1), "=r"(r2), "=r"(r3) : "r"(a) : "memory");
}
__device__ __forceinline__ void mma16816(float* d, const uint32_t* a,
                                         uint32_t b0, uint32_t b1) {
    asm volatile(
        "mma.sync.aligned.m16n8k16.row.col.f32.bf16.bf16.f32 "
        "{%0,%1,%2,%3}, {%4,%5,%6,%7}, {%8,%9}, {%0,%1,%2,%3};"
        : "+f"(d[0]), "+f"(d[1]), "+f"(d[2]), "+f"(d[3])
        : "r"(a[0]), "r"(a[1]), "r"(a[2]), "r"(a[3]), "r"(b0), "r"(b1));
}

// Convert one 64x64 fp32 W level into swizzled bf16 hi/lo smem images (256 thr).
__device__ __forceinline__ void conv_B(const float* __restrict__ Wk,
                                       char* dst_hi, char* dst_lo, int tid) {
    const int o = tid >> 2, i0 = (tid & 3) * 16;
    const float4* wr = (const float4*)(Wk + o * 64 + i0);
    uint32_t h[8], l[8];
    #pragma unroll
    for (int u = 0; u < 4; ++u) {
        float4 q = wr[u];
        uint32_t h0 = cvt2(q.x, q.y);
        uint32_t h1 = cvt2(q.z, q.w);
        h[u * 2 + 0] = h0;
        h[u * 2 + 1] = h1;
        l[u * 2 + 0] = cvt2(q.x - lo16f(h0), q.y - hi16f(h0));
        l[u * 2 + 1] = cvt2(q.z - lo16f(h1), q.w - hi16f(h1));
    }
    uint32_t off0 = SW128((uint32_t)(o * 128 + i0 * 2));
    uint32_t off1 = SW128((uint32_t)(o * 128 + i0 * 2 + 16));
    *(uint4*)(dst_hi + off0) = make_uint4(h[0], h[1], h[2], h[3]);
    *(uint4*)(dst_hi + off1) = make_uint4(h[4], h[5], h[6], h[7]);
    *(uint4*)(dst_lo + off0) = make_uint4(l[0], l[1], l[2], l[3]);
    *(uint4*)(dst_lo + off1) = make_uint4(l[4], l[5], l[6], l[7]);
}

// ---------------------------------------------------------------------------
// 32-row warp tile: D[2][8][4] = X32 @ W^T (3-product bf16 split).
// seg = 8704B region (2 A-segs: mt*4352; hi @+0, lo @+2176).
// B ldsm'd once per (s,np) feeds BOTH m16 tiles -> half B traffic per row.
// ---------------------------------------------------------------------------
__device__ __forceinline__ void mma_tile32(
    const float* __restrict__ X32, char* segp, uint32_t sseg,
    uint32_t sb_hi, uint32_t sb_lo, int lane, float D[2][8][4])
{
    const int r = lane >> 4;            // 0/1
    const int c4v = lane & 15;          // float4 col index

    // batched loads: 16 LDG.128 per thread (32 rows)
    float4 q[16];
    #pragma unroll
    for (int mt = 0; mt < 2; ++mt)
        #pragma unroll
        for (int i = 0; i < 8; ++i)
            q[mt * 8 + i] = *(const float4*)(X32 + (size_t)(mt * 16 + i * 2 + r) * F + c4v * 4);

    __syncwarp();
    #pragma unroll
    for (int mt = 0; mt < 2; ++mt)
        #pragma unroll
        for (int i = 0; i < 8; ++i) {
            float4 v = q[mt * 8 + i];
            uint32_t h0 = cvt2(v.x, v.y);
            uint32_t h1 = cvt2(v.z, v.w);
            uint32_t l0 = cvt2(v.x - lo16f(h0), v.y - hi16f(h0));
            uint32_t l1 = cvt2(v.z - lo16f(h1), v.w - hi16f(h1));
            uint32_t off = SW128((uint32_t)((i * 2 + r) * 128 + c4v * 8));
            *(ull*)(segp + mt * 4352 + off)        = (ull)h0 | ((ull)h1 << 32);
            *(ull*)(segp + mt * 4352 + 2176 + off) = (ull)l0 | ((ull)l1 << 32);
        }
    __syncwarp();

    #pragma unroll
    for (int mt = 0; mt < 2; ++mt)
        #pragma unroll
        for (int nt = 0; nt < 8; ++nt)
            #pragma unroll
            for (int rr = 0; rr < 4; ++rr) D[mt][nt][rr] = 0.f;

    const int arow = ((lane >> 3) & 1) * 8 + (lane & 7);
    const int acho = (lane >> 4) & 1;
    const int brow = ((lane >> 4) & 1) * 8 + (lane & 7);
    const int bcho = (lane >> 3) & 1;

    #pragma unroll
    for (int s = 0; s < 4; ++s) {
        uint32_t aoff = SW128((uint32_t)(arow * 128 + (2 * s + acho) * 16));
        uint32_t ah0[4], al0[4], ah1[4], al1[4];
        ldsm4(sseg + aoff,               ah0[0], ah0[1], ah0[2], ah0[3]);
        ldsm4(sseg + 2176 + aoff,        al0[0], al0[1], al0[2], al0[3]);
        ldsm4(sseg + 4352 + aoff,        ah1[0], ah1[1], ah1[2], ah1[3]);
        ldsm4(sseg + 4352 + 2176 + aoff, al1[0], al1[1], al1[2], al1[3]);
        #pragma unroll
        for (int np = 0; np < 4; ++np) {
            uint32_t boff = SW128((uint32_t)((np * 16 + brow) * 128 + (2 * s + bcho) * 16));
            uint32_t bh[4], bl[4];
            ldsm4(sb_hi + boff, bh[0], bh[1], bh[2], bh[3]);
            ldsm4(sb_lo + boff, bl[0], bl[1], bl[2], bl[3]);
            mma16816(D[0][np * 2 + 0], ah0, bh[0], bh[1]);
            mma16816(D[0][np * 2 + 0], al0, bh[0], bh[1]);
            mma16816(D[0][np * 2 + 0], ah0, bl[0], bl[1]);
            mma16816(D[0][np * 2 + 1], ah0, bh[2], bh[3]);
            mma16816(D[0][np * 2 + 1], al0, bh[2], bh[3]);
            mma16816(D[0][np * 2 + 1], ah0, bl[2], bl[3]);
            mma16816(D[1][np * 2 + 0], ah1, bh[0], bh[1]);
            mma16816(D[1][np * 2 + 0], al1, bh[0], bh[1]);
            mma16816(D[1][np * 2 + 0], ah1, bl[0], bl[1]);
            mma16816(D[1][np * 2 + 1], ah1, bh[2], bh[3]);
            mma16816(D[1][np * 2 + 1], al1, bh[2], bh[3]);
            mma16816(D[1][np * 2 + 1], ah1, bl[2], bl[3]);
        }
    }
    __syncwarp();   // all ldsm done before caller reuses seg as out-stage
}

// Store a warp's 32-row D into its stage region (2176 floats, pitch P).
__device__ __forceinline__ void stage_D32(float* seg, const float D[2][8][4],
                                          int lane, const float* bias /*or null*/)
{
    const int gg = lane >> 2, t2 = (lane & 3) * 2;
    #pragma unroll
    for (int mt = 0; mt < 2; ++mt)
        #pragma unroll
        for (int ntl = 0; ntl < 8; ++ntl) {
            const int c = ntl * 8 + t2;
            float b0 = bias ? bias[c] : 0.f, b1 = bias ? bias[c + 1] : 0.f;
            *(float2*)(seg + (mt * 16 + gg) * P + c) =
                make_float2(D[mt][ntl][0] + b0, D[mt][ntl][1] + b1);
            *(float2*)(seg + (mt * 16 + gg + 8) * P + c) =
                make_float2(D[mt][ntl][2] + b0, D[mt][ntl][3] + b1);
        }
}

// ---------------------------------------------------------------------------
// Y producer (persistent): CTAs [0,256): HMMA 256-row jobs over k=3..7
// (16 jobs/batch -> 512 total); CTAs [256,288): scalar small levels k=8..14.
// ---------------------------------------------------------------------------
__global__ __launch_bounds__(256, 2) void heap_mm_Y(
    const float* __restrict__ X, const float* __restrict__ W,
    const float* __restrict__ Bv)
{
    extern __shared__ char dsm[];
    const int tid = threadIdx.x;
    const int lane = tid & 31, warp = tid >> 5;
    const uint32_t sbase = smem_u32(dsm);

    if (blockIdx.x < YGRID_HMMA) {
        char* segp = dsm + YSTG + warp * 8704;
        const uint32_t sseg = sbase + YSTG + warp * 8704;
        float* segf = (float*)segp;
        int prevk = -1;
        #pragma unroll 1
        for (int e = blockIdx.x * 2; e < blockIdx.x * 2 + 2; ++e) {
            const int j = e >> 5, b = e & 31;
            int k, a0r, nr;
            if (j < 8)       { k = 3; a0r = j * 256;        nr = 256; }
            else if (j < 12) { k = 4; a0r = (j - 8) * 256;  nr = 256; }
            else if (j < 14) { k = 5; a0r = (j - 12) * 256; nr = 256; }
            else if (j == 14){ k = 6; a0r = 0;              nr = 256; }
            else             { k = 7; a0r = 0;              nr = 128; }

            if (k != prevk) {
                __syncthreads();
                conv_B(W + (size_t)k * F * F, dsm + YB_HI, dsm + YB_LO, tid);
                __syncthreads();
                prevk = k;
            }

            if (warp * 32 < nr) {
                float D[2][8][4];
                mma_tile32(X + ((size_t)b * NODES + a0r + warp * 32) * F,
                           segp, sseg, sbase + YB_HI, sbase + YB_LO, lane, D);
                stage_D32(segf, D, lane, nullptr);
                __syncwarp();

                const int c4 = lane & 15;
                float4 bq = *(const float4*)(Bv + k * F + c4 * 4);
                float* yg = g_Y + YOFF(k) * (BATCH * F)
                                + ((size_t)b * (NODES >> k) + a0r + warp * 32) * F;
                #pragma unroll
                for (int it = 0; it < 16; ++it) {
                    const int rr = it * 2 + (lane >> 4);
                    float4 v = *(const float4*)(segf + rr * P + c4 * 4);
                    v.x += bq.x; v.y += bq.y; v.z += bq.z; v.w += bq.w;
                    *(float4*)(yg + (size_t)rr * F + c4 * 4) = v;
                }
                __syncwarp();
            }
        }
    } else {
        // small levels k = 8..14: 224 jobs over 32 CTAs (7 each)
        float* ws = (float*)dsm;                      // 16KB overlay
        const int o = tid & 63, rg = tid >> 6;
        const int bx = blockIdx.x - YGRID_HMMA;
        int prevk = -1;
        for (int e = bx * 7; e < min(bx * 7 + 7, 224); ++e) {
            const int k = 8 + (e >> 5);
            const int b = e & 31;
            const int n = NODES >> k;
            if (k != prevk) {
                __syncthreads();
                const float* wk = W + (size_t)k * F * F;
                for (int idx = tid; idx < F * F; idx += 256)
                    ws[(idx & 63) * 64 + (idx >> 6)] = wk[idx];
                __syncthreads();
                prevk = k;
            }
            float* yg = g_Y + YOFF(k) * (BATCH * F) + (size_t)b * n * F;
            for (int a = rg; a < n; a += 4) {
                const float* Xb = X + ((size_t)b * NODES + a) * F;
                float s0 = 0.f, s1 = 0.f, s2 = 0.f, s3 = 0.f;
                #pragma unroll
                for (int i = 0; i < 64; i += 4) {
                    s0 = fmaf(__ldg(Xb + i + 0), ws[(i + 0) * 64 + o], s0);
                    s1 = fmaf(__ldg(Xb + i + 1), ws[(i + 1) * 64 + o], s1);
                    s2 = fmaf(__ldg(Xb + i + 2), ws[(i + 2) * 64 + o], s2);
                    s3 = fmaf(__ldg(Xb + i + 3), ws[(i + 3) * 64 + o], s3);
                }
                yg[(size_t)a * F + o] = Bv[k * F + o] + ((s0 + s1) + (s2 + s3));
            }
        }
    }
}

// ---------------------------------------------------------------------------
// Final (persistent, static warp roles):
//   warps 0-3: main 32 rows each (W0)          -> stage rows 0..127
//   warps 4-5: Y1   32 rows each (W1, +b1)     -> stage rows 128..191
//   warp  6  : Y2   32 rows      (W2, +b2)     -> stage rows 192..223
//   warp  7  : G3 gather, 16 rows              -> stage rows 224..239
//   merge: out[j] = main + b0 + [j>=1]Y1[j>>1] + [j>=2]Y2[j>>2] + [j>=4]G3[j>>3]
// ---------------------------------------------------------------------------
__global__ __launch_bounds__(256, 2) void heap_mm_final(
    const float* __restrict__ X, const float* __restrict__ W,
    const float* __restrict__ Bv, float* __restrict__ out)
{
    extern __shared__ char dsm[];
    const int tid = threadIdx.x;
    const int lane = tid & 31, warp = tid >> 5;
    const uint32_t sbase = smem_u32(dsm);
    float* stageF = (float*)(dsm + FSTG);

    conv_B(W,        dsm + FB0HI, dsm + FB0LO, tid);
    conv_B(W + 4096, dsm + FB1HI, dsm + FB1LO, tid);
    conv_B(W + 8192, dsm + FB2HI, dsm + FB2LO, tid);

    const int J = 128 * 32, CH = (J + FGRID - 1) / FGRID;   // 14
    const int e0 = blockIdx.x * CH;
    const int e1 = min(e0 + CH, J);

    const int c4 = tid & 15;
    const float4 b0q = *(const float4*)(Bv + c4 * 4);

    for (int e = e0; e < e1; ++e) {
        const int b = e >> 7;
        const int a0 = (e & 127) * 128;
        const int p0 = a0 >> 1, q0 = a0 >> 2, r0 = a0 >> 3;

        __syncthreads();   // previous merge done; stage region free

        if (warp < 7) {
            char* segp = dsm + FSTG + warp * 8704;
            const uint32_t sseg = sbase + FSTG + warp * 8704;
            const float* Xw;
            uint32_t sbH, sbL;
            const float* bias;
            if (warp < 4) {
                Xw = X + ((size_t)b * NODES + a0 + warp * 32) * F;
                sbH = sbase + FB0HI; sbL = sbase + FB0LO; bias = nullptr;
            } else if (warp < 6) {
                Xw = X + ((size_t)b * NODES + p0 + (warp - 4) * 32) * F;
                sbH = sbase + FB1HI; sbL = sbase + FB1LO; bias = Bv + F;
            } else {
                Xw = X + ((size_t)b * NODES + q0) * F;
                sbH = sbase + FB2HI; sbL = sbase + FB2LO; bias = Bv + 2 * F;
            }
            float D[2][8][4];
            mma_tile32(Xw, segp, sseg, sbH, sbL, lane, D);
            stage_D32(stageF + warp * 2176, D, lane, bias);
        } else {
            // G3 gather: 16 rows, 2 phases of 8 rows x 4 quarters
            #pragma unroll
            for (int ph = 0; ph < 2; ++ph) {
                const int rl = ph * 8 + (lane >> 2);
                const int r = r0 + rl;
                const int fq = (lane & 3) * 16;
                const int level = r ? (32 - __clz((unsigned)r)) : 0;
                float4 a0v = make_float4(0.f, 0.f, 0.f, 0.f);
                float4 a1v = a0v, a2v = a0v, a3v = a0v;
                #pragma unroll
                for (int kp = 0; kp < 12; ++kp) {
                    if (level >= kp) {
                        const int kk = kp + 3;
                        const float4* src = (const float4*)(
                            g_Y + YOFF(kk) * (BATCH * F)
                                + ((size_t)b * (NODES >> kk) + (r >> kp)) * F + fq);
                        float4 s0 = src[0], s1 = src[1], s2 = src[2], s3 = src[3];
                        a0v.x += s0.x; a0v.y += s0.y; a0v.z += s0.z; a0v.w += s0.w;
                        a1v.x += s1.x; a1v.y += s1.y; a1v.z += s1.z; a1v.w += s1.w;
                        a2v.x += s2.x; a2v.y += s2.y; a2v.z += s2.z; a2v.w += s2.w;
                        a3v.x += s3.x; a3v.y += s3.y; a3v.z += s3.z; a3v.w += s3.w;
                    }
                }
                float4* gd = (float4*)(stageF + (224 + rl) * P + fq);
                gd[0] = a0v; gd[1] = a1v; gd[2] = a2v; gd[3] = a3v;
            }
        }

        __syncthreads();   // all stage rows complete

        // ---- coalesced merge + store ----
        float* ob = out + ((size_t)b * NODES + a0) * F;
        #pragma unroll
        for (int it = 0; it < 8; ++it) {
            const int row = it * 16 + (tid >> 4);
            const int j = a0 + row;
            float4 v = *(const float4*)(stageF + row * P + c4 * 4);
            v.x += b0q.x; v.y += b0q.y; v.z += b0q.z; v.w += b0q.w;
            if (j >= 1) {
                float4 y1 = *(const float4*)(stageF + (128 + (row >> 1)) * P + c4 * 4);
                v.x += y1.x; v.y += y1.y; v.z += y1.z; v.w += y1.w;
            }
            if (j >= 2) {
                float4 y2 = *(const float4*)(stageF + (192 + (row >> 2)) * P + c4 * 4);
                v.x += y2.x; v.y += y2.y; v.z += y2.z; v.w += y2.w;
            }
            if (j >= 4) {
                float4 g3 = *(const float4*)(stageF + (224 + (row >> 3)) * P + c4 * 4);
                v.x += g3.x; v.y += g3.y; v.z += g3.z; v.w += g3.w;
            }
            *(float4*)(ob + (size_t)row * F + c4 * 4) = v;
        }
    }
}

// ---------------------------------------------------------------------------
extern "C" void kernel_launch(void* const* d_in, const int* in_sizes, int n_in,
                              void* d_out, int out_size) {
    const float* X  = (const float*)d_in[0];   // [32, 16384, 64]
    const float* W  = (const float*)d_in[1];   // [15, 64, 64]
    const float* Bv = (const float*)d_in[2];   // [15, 64]
    float* out = (float*)d_out;                // [32, 16384, 64]

    cudaFuncSetAttribute(heap_mm_Y,
                         cudaFuncAttributeMaxDynamicSharedMemorySize, SMY_TOTAL);
    cudaFuncSetAttribute(heap_mm_final,
                         cudaFuncAttributeMaxDynamicSharedMemorySize, SMF_TOTAL);

    heap_mm_Y     <<<YGRID, 256, SMY_TOTAL>>>(X, W, Bv);
    heap_mm_final <<<FGRID, 256, SMF_TOTAL>>>(X, W, Bv, out);
}

// round 14
// speedup vs baseline: 1.0847x; 1.0847x over previous
#include <cuda_runtime.h>
#include <cuda_bf16.h>
#include <cstdint>

#define NODES 16384
#define BATCH 32
#define F 64

typedef unsigned long long ull;

// Y_k for k=3..14 (level k starts at row YOFF(k); k<3 unused).
__device__ float g_Y[(size_t)16383 * BATCH * F];

__host__ __device__ constexpr size_t YOFF(int k) {   // k >= 1
    return (size_t)(16384 - (16384 >> (k - 1)));
}

#define SW128(x) ((x) ^ (((x) >> 3) & 0x70))

// ---- final kernel dynamic smem layout (bytes) ----
#define FB0HI 0
#define FB0LO 8192
#define FB1HI 16384
#define FB1LO 24576
#define FB2HI 32768
#define FB2LO 40960
#define FSTG  49152                 // stage region: 8 segs x 4352 = 34816
#define SEG   4352                  // per-warp seg: A hi @0 (2KB), A lo @2176 (2KB)
#define FY1S  (FSTG + 8 * SEG)      // 83968: 64 x 68 fp32
#define FY2S  (FY1S + 17408)        // 32 x 68 fp32
#define FG3S  (FY2S + 8704)         // 16 x 68 fp32
#define SMF_TOTAL (FG3S + 4352)     // 114432
#define P 68                        // stage pitch in floats (272 B)

// ---- Y kernel dynamic smem ----
#define YB_HI 0
#define YB_LO 8192
#define YSTG  16384
#define SMY_TOTAL (YSTG + 8 * SEG)  // 51200

#define FGRID 296
#define YGRID_HMMA 296
#define YGRID_SMALL 32
#define YGRID (YGRID_HMMA + YGRID_SMALL)

// ---------------- helpers ----------------
__device__ __forceinline__ uint32_t smem_u32(const void* p) {
    uint32_t a;
    asm("{ .reg .u64 t; cvta.to.shared.u64 t, %1; cvt.u32.u64 %0, t; }" : "=r"(a) : "l"(p));
    return a;
}
__device__ __forceinline__ void pfL2(const void* p) {
    asm volatile("prefetch.global.L2 [%0];" :: "l"(p));
}
// pack: low half = lo, high half = hi
__device__ __forceinline__ uint32_t cvt2(float lo, float hi) {
    uint32_t r; asm("cvt.rn.bf16x2.f32 %0, %1, %2;" : "=r"(r) : "f"(hi), "f"(lo)); return r;
}
__device__ __forceinline__ float lo16f(uint32_t u) { return __uint_as_float(u << 16); }
__device__ __forceinline__ float hi16f(uint32_t u) { return __uint_as_float(u & 0xffff0000u); }

__device__ __forceinline__ void ldsm4(uint32_t a, uint32_t& r0, uint32_t& r1,
                                      uint32_t& r2, uint32_t& r3) {
    asm volatile("ldmatrix.sync.aligned.m8n8.x4.shared.b16 {%0,%1,%2,%3}, [%4];"
                 : "=r"(r0), "=r"(r1), "=r"(r2), "=r"(r3) : "r"(a) : "memory");
}
__device__ __forceinline__ void mma16816(float* d, const uint32_t* a,
                                         uint32_t b0, uint32_t b1) {
    asm volatile(
        "mma.sync.aligned.m16n8k16.row.col.f32.bf16.bf16.f32 "
        "{%0,%1,%2,%3}, {%4,%5,%6,%7}, {%8,%9}, {%0,%1,%2,%3};"
        : "+f"(d[0]), "+f"(d[1]), "+f"(d[2]), "+f"(d[3])
        : "r"(a[0]), "r"(a[1]), "r"(a[2]), "r"(a[3]), "r"(b0), "r"(b1));
}

// Convert one 64x64 fp32 W level into swizzled bf16 hi/lo smem images (256 thr).
__device__ __forceinline__ void conv_B(const float* __restrict__ Wk,
                                       char* dst_hi, char* dst_lo, int tid) {
    const int o = tid >> 2, i0 = (tid & 3) * 16;
    const float4* wr = (const float4*)(Wk + o * 64 + i0);
    uint32_t h[8], l[8];
    #pragma unroll
    for (int u = 0; u < 4; ++u) {
        float4 q = wr[u];
        uint32_t h0 = cvt2(q.x, q.y);
        uint32_t h1 = cvt2(q.z, q.w);
        h[u * 2 + 0] = h0;
        h[u * 2 + 1] = h1;
        l[u * 2 + 0] = cvt2(q.x - lo16f(h0), q.y - hi16f(h0));
        l[u * 2 + 1] = cvt2(q.z - lo16f(h1), q.w - hi16f(h1));
    }
    uint32_t off0 = SW128((uint32_t)(o * 128 + i0 * 2));
    uint32_t off1 = SW128((uint32_t)(o * 128 + i0 * 2 + 16));
    *(uint4*)(dst_hi + off0) = make_uint4(h[0], h[1], h[2], h[3]);
    *(uint4*)(dst_hi + off1) = make_uint4(h[4], h[5], h[6], h[7]);
    *(uint4*)(dst_lo + off0) = make_uint4(l[0], l[1], l[2], l[3]);
    *(uint4*)(dst_lo + off1) = make_uint4(l[4], l[5], l[6], l[7]);
}

// ---------------------------------------------------------------------------
// Stage 16 X rows into this warp's smem seg as swizzled bf16 hi/lo via
// coalesced LDG.128, then ldmatrix the A fragments for all 4 k-chunks.
// ---------------------------------------------------------------------------
__device__ __forceinline__ void stage_A_frags(
    const float* __restrict__ Xrow, char* segp, uint32_t sseg, int lane,
    uint32_t ah[4][4], uint32_t al[4][4])
{
    const int r = lane >> 4;
    const int c4 = lane & 15;
    float4 q[8];
    #pragma unroll
    for (int i = 0; i < 8; ++i)
        q[i] = *(const float4*)(Xrow + (size_t)(i * 2 + r) * F + c4 * 4);

    __syncwarp();
    #pragma unroll
    for (int i = 0; i < 8; ++i) {
        uint32_t h0 = cvt2(q[i].x, q[i].y);
        uint32_t h1 = cvt2(q[i].z, q[i].w);
        uint32_t l0 = cvt2(q[i].x - lo16f(h0), q[i].y - hi16f(h0));
        uint32_t l1 = cvt2(q[i].z - lo16f(h1), q[i].w - hi16f(h1));
        uint32_t off = SW128((uint32_t)((i * 2 + r) * 128 + c4 * 8));
        *(ull*)(segp + off)        = (ull)h0 | ((ull)h1 << 32);
        *(ull*)(segp + 2176 + off) = (ull)l0 | ((ull)l1 << 32);
    }
    __syncwarp();

    const int arow = ((lane >> 3) & 1) * 8 + (lane & 7);
    const int acho = (lane >> 4) & 1;
    #pragma unroll
    for (int s = 0; s < 4; ++s) {
        uint32_t off = SW128((uint32_t)(arow * 128 + (2 * s + acho) * 16));
        ldsm4(sseg + off,        ah[s][0], ah[s][1], ah[s][2], ah[s][3]);
        ldsm4(sseg + 2176 + off, al[s][0], al[s][1], al[s][2], al[s][3]);
    }
    __syncwarp();
}

// MMA from prebuilt A fragments against B images (hi/lo), 3-product split.
__device__ __forceinline__ void mma_from_frags(
    const uint32_t ah[4][4], const uint32_t al[4][4],
    uint32_t sb_hi, uint32_t sb_lo, int lane, float D[8][4])
{
    const int brow = ((lane >> 4) & 1) * 8 + (lane & 7);
    const int bcho = (lane >> 3) & 1;

    #pragma unroll
    for (int nt = 0; nt < 8; ++nt)
        #pragma unroll
        for (int rr = 0; rr < 4; ++rr) D[nt][rr] = 0.f;

    #pragma unroll
    for (int s = 0; s < 4; ++s) {
        #pragma unroll
        for (int np = 0; np < 4; ++np) {
            uint32_t boff = SW128((uint32_t)((np * 16 + brow) * 128 + (2 * s + bcho) * 16));
            uint32_t bh[4], bl[4];
            ldsm4(sb_hi + boff, bh[0], bh[1], bh[2], bh[3]);
            ldsm4(sb_lo + boff, bl[0], bl[1], bl[2], bl[3]);
            mma16816(D[np * 2 + 0], ah[s], bh[0], bh[1]);
            mma16816(D[np * 2 + 0], al[s], bh[0], bh[1]);
            mma16816(D[np * 2 + 0], ah[s], bl[0], bl[1]);
            mma16816(D[np * 2 + 1], ah[s], bh[2], bh[3]);
            mma16816(D[np * 2 + 1], al[s], bh[2], bh[3]);
            mma16816(D[np * 2 + 1], ah[s], bl[2], bl[3]);
        }
    }
}

// Store a warp's 16-row D tile into its stage seg (fp32, pitch P floats).
__device__ __forceinline__ void stage_D(float* seg, const float D[8][4],
                                        int lane, const float* bias /*or null*/)
{
    const int gg = lane >> 2, t2 = (lane & 3) * 2;
    #pragma unroll
    for (int ntl = 0; ntl < 8; ++ntl) {
        const int c = ntl * 8 + t2;
        float b0 = bias ? bias[c] : 0.f, b1 = bias ? bias[c + 1] : 0.f;
        *(float2*)(seg + gg * P + c)       = make_float2(D[ntl][0] + b0, D[ntl][1] + b1);
        *(float2*)(seg + (gg + 8) * P + c) = make_float2(D[ntl][2] + b0, D[ntl][3] + b1);
    }
}

// ---------------------------------------------------------------------------
// Y producer (persistent): CTAs [0,296) HMMA tiles k=3..7 (992 jobs);
// CTAs [296,328) scalar small levels k=8..14.
// ---------------------------------------------------------------------------
__global__ __launch_bounds__(256, 2) void heap_mm_Y(
    const float* __restrict__ X, const float* __restrict__ W,
    const float* __restrict__ Bv)
{
    extern __shared__ char dsm[];
    const int tid = threadIdx.x;
    const int lane = tid & 31, warp = tid >> 5;
    const uint32_t sbase = smem_u32(dsm);

    if (blockIdx.x < YGRID_HMMA) {
        char* segp = dsm + YSTG + warp * SEG;
        const uint32_t sseg = sbase + YSTG + warp * SEG;
        const int J = 31 * 32, CH = (J + YGRID_HMMA - 1) / YGRID_HMMA;  // 4
        const int e0 = blockIdx.x * CH;
        const int e1 = min(e0 + CH, J);
        int prevk = -1;
        for (int e = e0; e < e1; ++e) {
            const int b = e & 31;
            int rem = e >> 5, k = 3, nt = 16;
            while (rem >= nt) { rem -= nt; nt >>= 1; ++k; }
            const int a0 = rem * 128;

            if (k != prevk) {
                __syncthreads();
                conv_B(W + (size_t)k * F * F, dsm + YB_HI, dsm + YB_LO, tid);
                __syncthreads();
                prevk = k;
            }

            uint32_t ah[4][4], al[4][4];
            stage_A_frags(X + ((size_t)b * NODES + a0 + warp * 16) * F,
                          segp, sseg, lane, ah, al);
            float D[8][4];
            mma_from_frags(ah, al, sbase + YB_HI, sbase + YB_LO, lane, D);

            // prefetch next job's rows while we still have work to do
            if (e + 1 < e1) {
                const int bn = (e + 1) & 31;
                int remn = (e + 1) >> 5, kn = 3, ntn = 16;
                while (remn >= ntn) { remn -= ntn; ntn >>= 1; ++kn; }
                const int a0n = remn * 128;
                pfL2(X + ((size_t)bn * NODES + a0n + warp * 16 + (lane >> 1)) * F
                       + (lane & 1) * 32);
            }

            float* seg = (float*)segp;
            stage_D(seg, D, lane, nullptr);
            __syncwarp();

            const int c4 = lane & 15;
            float4 bq = *(const float4*)(Bv + k * F + c4 * 4);
            float* yg = g_Y + YOFF(k) * (BATCH * F) + ((size_t)b * (NODES >> k)) * F;
            #pragma unroll
            for (int it = 0; it < 8; ++it) {
                const int rr = it * 2 + (lane >> 4);
                float4 v = *(const float4*)(seg + rr * P + c4 * 4);
                v.x += bq.x; v.y += bq.y; v.z += bq.z; v.w += bq.w;
                *(float4*)(yg + (size_t)(a0 + warp * 16 + rr) * F + c4 * 4) = v;
            }
            __syncwarp();
        }
    } else {
        // small levels k = 8..14: 224 jobs over 32 CTAs (7 each)
        float* ws = (float*)dsm;                      // 16KB overlay
        const int o = tid & 63, rg = tid >> 6;
        const int bx = blockIdx.x - YGRID_HMMA;
        int prevk = -1;
        for (int e = bx * 7; e < min(bx * 7 + 7, 224); ++e) {
            const int k = 8 + (e >> 5);
            const int b = e & 31;
            const int n = NODES >> k;
            if (k != prevk) {
                __syncthreads();
                const float* wk = W + (size_t)k * F * F;
                for (int idx = tid; idx < F * F; idx += 256)
                    ws[(idx & 63) * 64 + (idx >> 6)] = wk[idx];
                __syncthreads();
                prevk = k;
            }
            float* yg = g_Y + YOFF(k) * (BATCH * F) + (size_t)b * n * F;
            for (int a = rg; a < n; a += 4) {
                const float* Xb = X + ((size_t)b * NODES + a) * F;
                float s0 = 0.f, s1 = 0.f, s2 = 0.f, s3 = 0.f;
                #pragma unroll
                for (int i = 0; i < 64; i += 4) {
                    s0 = fmaf(__ldg(Xb + i + 0), ws[(i + 0) * 64 + o], s0);
                    s1 = fmaf(__ldg(Xb + i + 1), ws[(i + 1) * 64 + o], s1);
                    s2 = fmaf(__ldg(Xb + i + 2), ws[(i + 2) * 64 + o], s2);
                    s3 = fmaf(__ldg(Xb + i + 3), ws[(i + 3) * 64 + o], s3);
                }
                yg[(size_t)a * F + o] = Bv[k * F + o] + ((s0 + s1) + (s2 + s3));
            }
        }
    }
}

// ---------------------------------------------------------------------------
// Final (persistent, Y1+Y2 fused, G3 gather, staged I/O, L2 prefetch pipeline):
//   warps 0-3: Y1s = X[p0..] @ W1^T + b1 ; warps 4-5: Y2s = X[q0..] @ W2^T + b2
//   warps 6-7: G3s[r] = sum Y_{kp+3}[r>>kp]
//   all: D0 = X[a0..] @ W0^T -> stage -> coalesced merge (+b0 +Y1s +Y2s +G3s)
// ---------------------------------------------------------------------------
__global__ __launch_bounds__(256, 2) void heap_mm_final(
    const float* __restrict__ X, const float* __restrict__ W,
    const float* __restrict__ Bv, float* __restrict__ out)
{
    extern __shared__ char dsm[];
    const int tid = threadIdx.x;
    const int lane = tid & 31, warp = tid >> 5;
    const uint32_t sbase = smem_u32(dsm);
    char* segp = dsm + FSTG + warp * SEG;
    const uint32_t sseg = sbase + FSTG + warp * SEG;
    float* Y1s = (float*)(dsm + FY1S);
    float* Y2s = (float*)(dsm + FY2S);
    float* G3s = (float*)(dsm + FG3S);
    float* stage = (float*)(dsm + FSTG);     // 128 rows x P floats

    conv_B(W,        dsm + FB0HI, dsm + FB0LO, tid);
    conv_B(W + 4096, dsm + FB1HI, dsm + FB1LO, tid);
    conv_B(W + 8192, dsm + FB2HI, dsm + FB2LO, tid);

    const int J = 128 * 32, CH = (J + FGRID - 1) / FGRID;   // 14
    const int e0 = blockIdx.x * CH;
    const int e1 = min(e0 + CH, J);

    const int c4 = tid & 15;
    const float4 b0q = *(const float4*)(Bv + c4 * 4);
    const int pr = lane >> 1, ph = (lane & 1) * 32;   // prefetch row/half

    // warm L2 for the first job (main + role rows)
    {
        const int b = e0 >> 7, a0 = (e0 & 127) * 128;
        pfL2(X + ((size_t)b * NODES + a0 + warp * 16 + pr) * F + ph);
        if (warp < 4)
            pfL2(X + ((size_t)b * NODES + (a0 >> 1) + warp * 16 + pr) * F + ph);
        else if (warp < 6)
            pfL2(X + ((size_t)b * NODES + (a0 >> 2) + (warp - 4) * 16 + pr) * F + ph);
    }

    for (int e = e0; e < e1; ++e) {
        const int b = e >> 7;
        const int a0 = (e & 127) * 128;
        const int p0 = a0 >> 1, q0 = a0 >> 2, r0 = a0 >> 3;

        __syncthreads();   // stage/Y1s/Y2s/G3s free; B images ready

        if (warp < 4) {
            uint32_t ah[4][4], al[4][4];
            stage_A_frags(X + ((size_t)b * NODES + p0 + warp * 16) * F,
                          segp, sseg, lane, ah, al);
            float D1[8][4];
            mma_from_frags(ah, al, sbase + FB1HI, sbase + FB1LO, lane, D1);
            stage_D(Y1s + warp * 16 * P, D1, lane, Bv + F);
        } else if (warp < 6) {
            uint32_t ah[4][4], al[4][4];
            stage_A_frags(X + ((size_t)b * NODES + q0 + (warp - 4) * 16) * F,
                          segp, sseg, lane, ah, al);
            float D2[8][4];
            mma_from_frags(ah, al, sbase + FB2HI, sbase + FB2LO, lane, D2);
            stage_D(Y2s + (warp - 4) * 16 * P, D2, lane, Bv + 2 * F);
        } else {
            const int t3 = tid - 192;
            const int rl = t3 >> 2;
            const int r = r0 + rl;
            const int fq = (t3 & 3) * 16;
            const int level = r ? (32 - __clz((unsigned)r)) : 0;
            float4 a0v = make_float4(0.f, 0.f, 0.f, 0.f);
            float4 a1v = a0v, a2v = a0v, a3v = a0v;
            #pragma unroll
            for (int kp = 0; kp < 12; ++kp) {
                if (level >= kp) {
                    const int kk = kp + 3;
                    const float4* src = (const float4*)(
                        g_Y + YOFF(kk) * (BATCH * F)
                            + ((size_t)b * (NODES >> kk) + (r >> kp)) * F + fq);
                    float4 s0 = src[0], s1 = src[1], s2 = src[2], s3 = src[3];
                    a0v.x += s0.x; a0v.y += s0.y; a0v.z += s0.z; a0v.w += s0.w;
                    a1v.x += s1.x; a1v.y += s1.y; a1v.z += s1.z; a1v.w += s1.w;
                    a2v.x += s2.x; a2v.y += s2.y; a2v.z += s2.z; a2v.w += s2.w;
                    a3v.x += s3.x; a3v.y += s3.y; a3v.z += s3.z; a3v.w += s3.w;
                }
            }
            float4* gd = (float4*)(G3s + rl * P + fq);
            gd[0] = a0v; gd[1] = a1v; gd[2] = a2v; gd[3] = a3v;
        }

        // ---- main tile W0 (all warps; rows were L2-prefetched) ----
        {
            uint32_t ah[4][4], al[4][4];
            stage_A_frags(X + ((size_t)b * NODES + a0 + warp * 16) * F,
                          segp, sseg, lane, ah, al);
            float D0[8][4];
            mma_from_frags(ah, al, sbase + FB0HI, sbase + FB0LO, lane, D0);
            stage_D(stage + warp * 16 * P, D0, lane, nullptr);
        }

        // prefetch next job's main + role rows into L2 before the merge
        if (e + 1 < e1) {
            const int bn = (e + 1) >> 7;
            const int a0n = ((e + 1) & 127) * 128;
            pfL2(X + ((size_t)bn * NODES + a0n + warp * 16 + pr) * F + ph);
            if (warp < 4)
                pfL2(X + ((size_t)bn * NODES + (a0n >> 1) + warp * 16 + pr) * F + ph);
            else if (warp < 6)
                pfL2(X + ((size_t)bn * NODES + (a0n >> 2) + (warp - 4) * 16 + pr) * F + ph);
        }
        __syncthreads();   // all stage buffers complete

        // ---- coalesced merge + store ----
        float* ob = out + ((size_t)b * NODES + a0) * F;
        #pragma unroll
        for (int it = 0; it < 8; ++it) {
            const int row = it * 16 + (tid >> 4);
            const int j = a0 + row;
            float4 v = *(const float4*)(stage + row * P + c4 * 4);
            v.x += b0q.x; v.y += b0q.y; v.z += b0q.z; v.w += b0q.w;
            if (j >= 1) {
                float4 y1 = *(const float4*)(Y1s + (row >> 1) * P + c4 * 4);
                v.x += y1.x; v.y += y1.y; v.z += y1.z; v.w += y1.w;
            }
            if (j >= 2) {
                float4 y2 = *(const float4*)(Y2s + (row >> 2) * P + c4 * 4);
                v.x += y2.x; v.y += y2.y; v.z += y2.z; v.w += y2.w;
            }
            if (j >= 4) {
                float4 g3 = *(const float4*)(G3s + (row >> 3) * P + c4 * 4);
                v.x += g3.x; v.y += g3.y; v.z += g3.z; v.w += g3.w;
            }
            *(float4*)(ob + (size_t)row * F + c4 * 4) = v;
        }
    }
}

// ---------------------------------------------------------------------------
extern "C" void kernel_launch(void* const* d_in, const int* in_sizes, int n_in,
                              void* d_out, int out_size) {
    const float* X  = (const float*)d_in[0];   // [32, 16384, 64]
    const float* W  = (const float*)d_in[1];   // [15, 64, 64]
    const float* Bv = (const float*)d_in[2];   // [15, 64]
    float* out = (float*)d_out;                // [32, 16384, 64]

    cudaFuncSetAttribute(heap_mm_Y,
                         cudaFuncAttributeMaxDynamicSharedMemorySize, SMY_TOTAL);
    cudaFuncSetAttribute(heap_mm_final,
                         cudaFuncAttributeMaxDynamicSharedMemorySize, SMF_TOTAL);

    heap_mm_Y     <<<YGRID, 256, SMY_TOTAL>>>(X, W, Bv);
    heap_mm_final <<<FGRID, 256, SMF_TOTAL>>>(X, W, Bv, out);
}

// round 15
// speedup vs baseline: 1.1222x; 1.0346x over previous
#include <cuda_runtime.h>
#include <cuda_bf16.h>
#include <cstdint>

#define NODES 16384
#define BATCH 32
#define F 64

typedef unsigned long long ull;

// Y_k for k=3..14 (level k starts at row YOFF(k); k<3 unused).
__device__ float g_Y[(size_t)16383 * BATCH * F];

__host__ __device__ constexpr size_t YOFF(int k) {   // k >= 1
    return (size_t)(16384 - (16384 >> (k - 1)));
}

#define SW128(x) ((x) ^ (((x) >> 3) & 0x70))

// ---- final kernel dynamic smem layout (bytes) ----
#define FB0HI 0
#define FB0LO 8192
#define FB1HI 16384
#define FB1LO 24576
#define FB2HI 32768
#define FB2LO 40960
#define FSTG  49152                 // stage region: 8 segs x 4352 = 34816
#define SEG   4352                  // per-warp seg: A hi @0 (2KB), A lo @2176 (2KB)
#define FY1S  (FSTG + 8 * SEG)      // 83968: 64 x 68 fp32
#define FY2S  (FY1S + 17408)        // 32 x 68 fp32
#define FG3S  (FY2S + 8704)         // 16 x 68 fp32
#define SMF_TOTAL (FG3S + 4352)     // 114432
#define P 68                        // stage pitch in floats (272 B)

// ---- Y kernel dynamic smem ----
#define YB_HI 0
#define YB_LO 8192
#define YSTG  16384
#define SMY_TOTAL (YSTG + 8 * SEG)  // 51200

#define FGRID 296
#define YGRID_HMMA 296
#define YGRID_SMALL 32
#define YGRID (YGRID_HMMA + YGRID_SMALL)

// ---------------- helpers ----------------
__device__ __forceinline__ uint32_t smem_u32(const void* p) {
    uint32_t a;
    asm("{ .reg .u64 t; cvta.to.shared.u64 t, %1; cvt.u32.u64 %0, t; }" : "=r"(a) : "l"(p));
    return a;
}
__device__ __forceinline__ void pfL2(const void* p) {
    asm volatile("prefetch.global.L2 [%0];" :: "l"(p));
}
// pack: low half = lo, high half = hi
__device__ __forceinline__ uint32_t cvt2(float lo, float hi) {
    uint32_t r; asm("cvt.rn.bf16x2.f32 %0, %1, %2;" : "=r"(r) : "f"(hi), "f"(lo)); return r;
}
__device__ __forceinline__ float lo16f(uint32_t u) { return __uint_as_float(u << 16); }
__device__ __forceinline__ float hi16f(uint32_t u) { return __uint_as_float(u & 0xffff0000u); }

__device__ __forceinline__ void ldsm4(uint32_t a, uint32_t& r0, uint32_t& r1,
                                      uint32_t& r2, uint32_t& r3) {
    asm volatile("ldmatrix.sync.aligned.m8n8.x4.shared.b16 {%0,%1,%2,%3}, [%4];"
                 : "=r"(r0), "=r"(r1), "=r"(r2), "=r"(r3) : "r"(a) : "memory");
}
__device__ __forceinline__ void mma16816(float* d, const uint32_t* a,
                                         uint32_t b0, uint32_t b1) {
    asm volatile(
        "mma.sync.aligned.m16n8k16.row.col.f32.bf16.bf16.f32 "
        "{%0,%1,%2,%3}, {%4,%5,%6,%7}, {%8,%9}, {%0,%1,%2,%3};"
        : "+f"(d[0]), "+f"(d[1]), "+f"(d[2]), "+f"(d[3])
        : "r"(a[0]), "r"(a[1]), "r"(a[2]), "r"(a[3]), "r"(b0), "r"(b1));
}

// Convert one 64x64 fp32 W level into swizzled bf16 hi/lo smem images (256 thr).
__device__ __forceinline__ void conv_B(const float* __restrict__ Wk,
                                       char* dst_hi, char* dst_lo, int tid) {
    const int o = tid >> 2, i0 = (tid & 3) * 16;
    const float4* wr = (const float4*)(Wk + o * 64 + i0);
    uint32_t h[8], l[8];
    #pragma unroll
    for (int u = 0; u < 4; ++u) {
        float4 q = wr[u];
        uint32_t h0 = cvt2(q.x, q.y);
        uint32_t h1 = cvt2(q.z, q.w);
        h[u * 2 + 0] = h0;
        h[u * 2 + 1] = h1;
        l[u * 2 + 0] = cvt2(q.x - lo16f(h0), q.y - hi16f(h0));
        l[u * 2 + 1] = cvt2(q.z - lo16f(h1), q.w - hi16f(h1));
    }
    uint32_t off0 = SW128((uint32_t)(o * 128 + i0 * 2));
    uint32_t off1 = SW128((uint32_t)(o * 128 + i0 * 2 + 16));
    *(uint4*)(dst_hi + off0) = make_uint4(h[0], h[1], h[2], h[3]);
    *(uint4*)(dst_hi + off1) = make_uint4(h[4], h[5], h[6], h[7]);
    *(uint4*)(dst_lo + off0) = make_uint4(l[0], l[1], l[2], l[3]);
    *(uint4*)(dst_lo + off1) = make_uint4(l[4], l[5], l[6], l[7]);
}

// ---------------------------------------------------------------------------
// Stage 16 X rows into this warp's smem seg as swizzled bf16 hi/lo via
// coalesced LDG.128, then ldmatrix the A fragments for all 4 k-chunks.
// ---------------------------------------------------------------------------
__device__ __forceinline__ void stage_A_frags(
    const float* __restrict__ Xrow, char* segp, uint32_t sseg, int lane,
    uint32_t ah[4][4], uint32_t al[4][4])
{
    const int r = lane >> 4;
    const int c4 = lane & 15;
    float4 q[8];
    #pragma unroll
    for (int i = 0; i < 8; ++i)
        q[i] = *(const float4*)(Xrow + (size_t)(i * 2 + r) * F + c4 * 4);

    __syncwarp();
    #pragma unroll
    for (int i = 0; i < 8; ++i) {
        uint32_t h0 = cvt2(q[i].x, q[i].y);
        uint32_t h1 = cvt2(q[i].z, q[i].w);
        uint32_t l0 = cvt2(q[i].x - lo16f(h0), q[i].y - hi16f(h0));
        uint32_t l1 = cvt2(q[i].z - lo16f(h1), q[i].w - hi16f(h1));
        uint32_t off = SW128((uint32_t)((i * 2 + r) * 128 + c4 * 8));
        *(ull*)(segp + off)        = (ull)h0 | ((ull)h1 << 32);
        *(ull*)(segp + 2176 + off) = (ull)l0 | ((ull)l1 << 32);
    }
    __syncwarp();

    const int arow = ((lane >> 3) & 1) * 8 + (lane & 7);
    const int acho = (lane >> 4) & 1;
    #pragma unroll
    for (int s = 0; s < 4; ++s) {
        uint32_t off = SW128((uint32_t)(arow * 128 + (2 * s + acho) * 16));
        ldsm4(sseg + off,        ah[s][0], ah[s][1], ah[s][2], ah[s][3]);
        ldsm4(sseg + 2176 + off, al[s][0], al[s][1], al[s][2], al[s][3]);
    }
    __syncwarp();
}

// MMA from prebuilt A fragments against B images (hi/lo), 3-product split.
__device__ __forceinline__ void mma_from_frags(
    const uint32_t ah[4][4], const uint32_t al[4][4],
    uint32_t sb_hi, uint32_t sb_lo, int lane, float D[8][4])
{
    const int brow = ((lane >> 4) & 1) * 8 + (lane & 7);
    const int bcho = (lane >> 3) & 1;

    #pragma unroll
    for (int nt = 0; nt < 8; ++nt)
        #pragma unroll
        for (int rr = 0; rr < 4; ++rr) D[nt][rr] = 0.f;

    #pragma unroll
    for (int s = 0; s < 4; ++s) {
        #pragma unroll
        for (int np = 0; np < 4; ++np) {
            uint32_t boff = SW128((uint32_t)((np * 16 + brow) * 128 + (2 * s + bcho) * 16));
            uint32_t bh[4], bl[4];
            ldsm4(sb_hi + boff, bh[0], bh[1], bh[2], bh[3]);
            ldsm4(sb_lo + boff, bl[0], bl[1], bl[2], bl[3]);
            mma16816(D[np * 2 + 0], ah[s], bh[0], bh[1]);
            mma16816(D[np * 2 + 0], al[s], bh[0], bh[1]);
            mma16816(D[np * 2 + 0], ah[s], bl[0], bl[1]);
            mma16816(D[np * 2 + 1], ah[s], bh[2], bh[3]);
            mma16816(D[np * 2 + 1], al[s], bh[2], bh[3]);
            mma16816(D[np * 2 + 1], ah[s], bl[2], bl[3]);
        }
    }
}

// Store a warp's 16-row D tile into its stage seg (fp32, pitch P floats).
__device__ __forceinline__ void stage_D(float* seg, const float D[8][4],
                                        int lane, const float* bias /*or null*/)
{
    const int gg = lane >> 2, t2 = (lane & 3) * 2;
    #pragma unroll
    for (int ntl = 0; ntl < 8; ++ntl) {
        const int c = ntl * 8 + t2;
        float b0 = bias ? bias[c] : 0.f, b1 = bias ? bias[c + 1] : 0.f;
        *(float2*)(seg + gg * P + c)       = make_float2(D[ntl][0] + b0, D[ntl][1] + b1);
        *(float2*)(seg + (gg + 8) * P + c) = make_float2(D[ntl][2] + b0, D[ntl][3] + b1);
    }
}

// ---------------------------------------------------------------------------
// Y producer (persistent): CTAs [0,296) HMMA tiles k=3..7 (992 jobs, BALANCED
// floor-partition); CTAs [296,328): one CTA per batch, one small-level job per
// k=8..14 (127 rows each -> perfectly balanced).
// ---------------------------------------------------------------------------
__global__ __launch_bounds__(256, 2) void heap_mm_Y(
    const float* __restrict__ X, const float* __restrict__ W,
    const float* __restrict__ Bv)
{
    extern __shared__ char dsm[];
    const int tid = threadIdx.x;
    const int lane = tid & 31, warp = tid >> 5;
    const uint32_t sbase = smem_u32(dsm);

    if (blockIdx.x < YGRID_HMMA) {
        char* segp = dsm + YSTG + warp * SEG;
        const uint32_t sseg = sbase + YSTG + warp * SEG;
        const int J = 31 * 32;
        const int e0 = (int)(((long long)blockIdx.x * J) / YGRID_HMMA);
        const int e1 = (int)(((long long)(blockIdx.x + 1) * J) / YGRID_HMMA);

        // warm L2 for first job
        if (e0 < e1) {
            const int b = e0 & 31;
            int rem = e0 >> 5, k = 3, nt = 16;
            while (rem >= nt) { rem -= nt; nt >>= 1; ++k; }
            pfL2(X + ((size_t)b * NODES + rem * 128 + warp * 16 + (lane >> 1)) * F
                   + (lane & 1) * 32);
        }

        int prevk = -1;
        for (int e = e0; e < e1; ++e) {
            const int b = e & 31;
            int rem = e >> 5, k = 3, nt = 16;
            while (rem >= nt) { rem -= nt; nt >>= 1; ++k; }
            const int a0 = rem * 128;

            if (k != prevk) {
                __syncthreads();
                conv_B(W + (size_t)k * F * F, dsm + YB_HI, dsm + YB_LO, tid);
                __syncthreads();
                prevk = k;
            }

            uint32_t ah[4][4], al[4][4];
            stage_A_frags(X + ((size_t)b * NODES + a0 + warp * 16) * F,
                          segp, sseg, lane, ah, al);
            float D[8][4];
            mma_from_frags(ah, al, sbase + YB_HI, sbase + YB_LO, lane, D);

            // prefetch next job's rows
            if (e + 1 < e1) {
                const int bn = (e + 1) & 31;
                int remn = (e + 1) >> 5, kn = 3, ntn = 16;
                while (remn >= ntn) { remn -= ntn; ntn >>= 1; ++kn; }
                const int a0n = remn * 128;
                pfL2(X + ((size_t)bn * NODES + a0n + warp * 16 + (lane >> 1)) * F
                       + (lane & 1) * 32);
            }

            float* seg = (float*)segp;
            stage_D(seg, D, lane, nullptr);
            __syncwarp();

            const int c4 = lane & 15;
            float4 bq = *(const float4*)(Bv + k * F + c4 * 4);
            float* yg = g_Y + YOFF(k) * (BATCH * F) + ((size_t)b * (NODES >> k)) * F;
            #pragma unroll
            for (int it = 0; it < 8; ++it) {
                const int rr = it * 2 + (lane >> 4);
                float4 v = *(const float4*)(seg + rr * P + c4 * 4);
                v.x += bq.x; v.y += bq.y; v.z += bq.z; v.w += bq.w;
                *(float4*)(yg + (size_t)(a0 + warp * 16 + rr) * F + c4 * 4) = v;
            }
            __syncwarp();
        }
    } else {
        // small levels: CTA = batch; one job per level k=8..14 (127 rows total)
        float* ws = (float*)dsm;                      // 16KB overlay
        const int o = tid & 63, rg = tid >> 6;
        const int b = blockIdx.x - YGRID_HMMA;        // 0..31 = batch

        // prefetch this batch's ancestor rows 0..63 (covers all small levels)
        if (tid < 128)
            pfL2(X + (size_t)b * NODES * F + tid * 32);

        for (int i = 0; i < 7; ++i) {
            const int k = 8 + i;
            const int n = NODES >> k;
            __syncthreads();
            const float* wk = W + (size_t)k * F * F;
            for (int idx = tid; idx < F * F; idx += 256)
                ws[(idx & 63) * 64 + (idx >> 6)] = wk[idx];
            __syncthreads();

            float* yg = g_Y + YOFF(k) * (BATCH * F) + (size_t)b * n * F;
            for (int a = rg; a < n; a += 4) {
                const float* Xb = X + ((size_t)b * NODES + a) * F;
                float s0 = 0.f, s1 = 0.f, s2 = 0.f, s3 = 0.f;
                #pragma unroll
                for (int i2 = 0; i2 < 64; i2 += 4) {
                    s0 = fmaf(__ldg(Xb + i2 + 0), ws[(i2 + 0) * 64 + o], s0);
                    s1 = fmaf(__ldg(Xb + i2 + 1), ws[(i2 + 1) * 64 + o], s1);
                    s2 = fmaf(__ldg(Xb + i2 + 2), ws[(i2 + 2) * 64 + o], s2);
                    s3 = fmaf(__ldg(Xb + i2 + 3), ws[(i2 + 3) * 64 + o], s3);
                }
                yg[(size_t)a * F + o] = Bv[k * F + o] + ((s0 + s1) + (s2 + s3));
            }
        }
    }
}

// ---------------------------------------------------------------------------
// Final (persistent, Y1+Y2 fused, G3 gather, staged I/O, L2 prefetch pipeline):
//   warps 0-3: Y1s = X[p0..] @ W1^T + b1 ; warps 4-5: Y2s = X[q0..] @ W2^T + b2
//   warps 6-7: G3s[r] = sum Y_{kp+3}[r>>kp]
//   all: D0 = X[a0..] @ W0^T -> stage -> coalesced merge (+b0 +Y1s +Y2s +G3s)
// ---------------------------------------------------------------------------
__global__ __launch_bounds__(256, 2) void heap_mm_final(
    const float* __restrict__ X, const float* __restrict__ W,
    const float* __restrict__ Bv, float* __restrict__ out)
{
    extern __shared__ char dsm[];
    const int tid = threadIdx.x;
    const int lane = tid & 31, warp = tid >> 5;
    const uint32_t sbase = smem_u32(dsm);
    char* segp = dsm + FSTG + warp * SEG;
    const uint32_t sseg = sbase + FSTG + warp * SEG;
    float* Y1s = (float*)(dsm + FY1S);
    float* Y2s = (float*)(dsm + FY2S);
    float* G3s = (float*)(dsm + FG3S);
    float* stage = (float*)(dsm + FSTG);     // 128 rows x P floats

    conv_B(W,        dsm + FB0HI, dsm + FB0LO, tid);
    conv_B(W + 4096, dsm + FB1HI, dsm + FB1LO, tid);
    conv_B(W + 8192, dsm + FB2HI, dsm + FB2LO, tid);

    const int J = 128 * 32, CH = (J + FGRID - 1) / FGRID;   // 14
    const int e0 = blockIdx.x * CH;
    const int e1 = min(e0 + CH, J);

    const int c4 = tid & 15;
    const float4 b0q = *(const float4*)(Bv + c4 * 4);
    const int pr = lane >> 1, ph = (lane & 1) * 32;   // prefetch row/half

    // warm L2 for the first job (main + role rows)
    {
        const int b = e0 >> 7, a0 = (e0 & 127) * 128;
        pfL2(X + ((size_t)b * NODES + a0 + warp * 16 + pr) * F + ph);
        if (warp < 4)
            pfL2(X + ((size_t)b * NODES + (a0 >> 1) + warp * 16 + pr) * F + ph);
        else if (warp < 6)
            pfL2(X + ((size_t)b * NODES + (a0 >> 2) + (warp - 4) * 16 + pr) * F + ph);
    }

    for (int e = e0; e < e1; ++e) {
        const int b = e >> 7;
        const int a0 = (e & 127) * 128;
        const int p0 = a0 >> 1, q0 = a0 >> 2, r0 = a0 >> 3;

        __syncthreads();   // stage/Y1s/Y2s/G3s free; B images ready

        if (warp < 4) {
            uint32_t ah[4][4], al[4][4];
            stage_A_frags(X + ((size_t)b * NODES + p0 + warp * 16) * F,
                          segp, sseg, lane, ah, al);
            float D1[8][4];
            mma_from_frags(ah, al, sbase + FB1HI, sbase + FB1LO, lane, D1);
            stage_D(Y1s + warp * 16 * P, D1, lane, Bv + F);
        } else if (warp < 6) {
            uint32_t ah[4][4], al[4][4];
            stage_A_frags(X + ((size_t)b * NODES + q0 + (warp - 4) * 16) * F,
                          segp, sseg, lane, ah, al);
            float D2[8][4];
            mma_from_frags(ah, al, sbase + FB2HI, sbase + FB2LO, lane, D2);
            stage_D(Y2s + (warp - 4) * 16 * P, D2, lane, Bv + 2 * F);
        } else {
            const int t3 = tid - 192;
            const int rl = t3 >> 2;
            const int r = r0 + rl;
            const int fq = (t3 & 3) * 16;
            const int level = r ? (32 - __clz((unsigned)r)) : 0;
            float4 a0v = make_float4(0.f, 0.f, 0.f, 0.f);
            float4 a1v = a0v, a2v = a0v, a3v = a0v;
            #pragma unroll
            for (int kp = 0; kp < 12; ++kp) {
                if (level >= kp) {
                    const int kk = kp + 3;
                    const float4* src = (const float4*)(
                        g_Y + YOFF(kk) * (BATCH * F)
                            + ((size_t)b * (NODES >> kk) + (r >> kp)) * F + fq);
                    float4 s0 = src[0], s1 = src[1], s2 = src[2], s3 = src[3];
                    a0v.x += s0.x; a0v.y += s0.y; a0v.z += s0.z; a0v.w += s0.w;
                    a1v.x += s1.x; a1v.y += s1.y; a1v.z += s1.z; a1v.w += s1.w;
                    a2v.x += s2.x; a2v.y += s2.y; a2v.z += s2.z; a2v.w += s2.w;
                    a3v.x += s3.x; a3v.y += s3.y; a3v.z += s3.z; a3v.w += s3.w;
                }
            }
            float4* gd = (float4*)(G3s + rl * P + fq);
            gd[0] = a0v; gd[1] = a1v; gd[2] = a2v; gd[3] = a3v;
        }

        // ---- main tile W0 (all warps; rows were L2-prefetched) ----
        {
            uint32_t ah[4][4], al[4][4];
            stage_A_frags(X + ((size_t)b * NODES + a0 + warp * 16) * F,
                          segp, sseg, lane, ah, al);
            float D0[8][4];
            mma_from_frags(ah, al, sbase + FB0HI, sbase + FB0LO, lane, D0);
            stage_D(stage + warp * 16 * P, D0, lane, nullptr);
        }

        // prefetch next job's main + role rows into L2 before the merge
        if (e + 1 < e1) {
            const int bn = (e + 1) >> 7;
            const int a0n = ((e + 1) & 127) * 128;
            pfL2(X + ((size_t)bn * NODES + a0n + warp * 16 + pr) * F + ph);
            if (warp < 4)
                pfL2(X + ((size_t)bn * NODES + (a0n >> 1) + warp * 16 + pr) * F + ph);
            else if (warp < 6)
                pfL2(X + ((size_t)bn * NODES + (a0n >> 2) + (warp - 4) * 16 + pr) * F + ph);
        }
        __syncthreads();   // all stage buffers complete

        // ---- coalesced merge + store ----
        float* ob = out + ((size_t)b * NODES + a0) * F;
        #pragma unroll
        for (int it = 0; it < 8; ++it) {
            const int row = it * 16 + (tid >> 4);
            const int j = a0 + row;
            float4 v = *(const float4*)(stage + row * P + c4 * 4);
            v.x += b0q.x; v.y += b0q.y; v.z += b0q.z; v.w += b0q.w;
            if (j >= 1) {
                float4 y1 = *(const float4*)(Y1s + (row >> 1) * P + c4 * 4);
                v.x += y1.x; v.y += y1.y; v.z += y1.z; v.w += y1.w;
            }
            if (j >= 2) {
                float4 y2 = *(const float4*)(Y2s + (row >> 2) * P + c4 * 4);
                v.x += y2.x; v.y += y2.y; v.z += y2.z; v.w += y2.w;
            }
            if (j >= 4) {
                float4 g3 = *(const float4*)(G3s + (row >> 3) * P + c4 * 4);
                v.x += g3.x; v.y += g3.y; v.z += g3.z; v.w += g3.w;
            }
            *(float4*)(ob + (size_t)row * F + c4 * 4) = v;
        }
    }
}

// ---------------------------------------------------------------------------
extern "C" void kernel_launch(void* const* d_in, const int* in_sizes, int n_in,
                              void* d_out, int out_size) {
    const float* X  = (const float*)d_in[0];   // [32, 16384, 64]
    const float* W  = (const float*)d_in[1];   // [15, 64, 64]
    const float* Bv = (const float*)d_in[2];   // [15, 64]
    float* out = (float*)d_out;                // [32, 16384, 64]

    cudaFuncSetAttribute(heap_mm_Y,
                         cudaFuncAttributeMaxDynamicSharedMemorySize, SMY_TOTAL);
    cudaFuncSetAttribute(heap_mm_final,
                         cudaFuncAttributeMaxDynamicSharedMemorySize, SMF_TOTAL);

    heap_mm_Y     <<<YGRID, 256, SMY_TOTAL>>>(X, W, Bv);
    heap_mm_final <<<FGRID, 256, SMF_TOTAL>>>(X, W, Bv, out);
}

// round 16
// speedup vs baseline: 1.1510x; 1.0256x over previous
#include <cuda_runtime.h>
#include <cuda_bf16.h>
#include <cstdint>

#define NODES 16384
#define BATCH 32
#define F 64

typedef unsigned long long ull;

// Y_k for k=3..14 (level k starts at row YOFF(k); k<3 unused).
__device__ float g_Y[(size_t)16383 * BATCH * F];

__host__ __device__ constexpr size_t YOFF(int k) {   // k >= 1
    return (size_t)(16384 - (16384 >> (k - 1)));
}

#define SW128(x) ((x) ^ (((x) >> 3) & 0x70))

// ---- final kernel dynamic smem layout (bytes) ----
#define FB0HI 0
#define FB0LO 8192
#define FB1HI 16384
#define FB1LO 24576
#define FB2HI 32768
#define FB2LO 40960
#define FSTG  49152                 // stage region: 8 segs x 4352 = 34816
#define SEG   4352                  // per-warp seg: A hi @0 (2KB), A lo @2176 (2KB)
#define FY1S  (FSTG + 8 * SEG)      // 83968: 64 x 68 fp32
#define FY2S  (FY1S + 17408)        // 32 x 68 fp32
#define FG3S  (FY2S + 8704)         // 16 x 68 fp32
#define SMF_TOTAL (FG3S + 4352)     // 114432
#define P 68                        // stage pitch in floats (272 B)

// ---- Y kernel dynamic smem ----
// HMMA branch: B @0/8192, segs @16384 + w*SEG.
// small branch: B8 @0/8192, B9 @16384/24576, B10 @32768/40960, segs @49152+w*SEG.
#define YB_HI 0
#define YB_LO 8192
#define YSTG  16384
#define SMY_TOTAL (49152 + 8 * SEG)  // 83968

#define FGRID 296
#define YGRID_HMMA 296
#define YGRID_SMALL 32
#define YGRID (YGRID_HMMA + YGRID_SMALL)

// ---------------- helpers ----------------
__device__ __forceinline__ uint32_t smem_u32(const void* p) {
    uint32_t a;
    asm("{ .reg .u64 t; cvta.to.shared.u64 t, %1; cvt.u32.u64 %0, t; }" : "=r"(a) : "l"(p));
    return a;
}
__device__ __forceinline__ void pfL2(const void* p) {
    asm volatile("prefetch.global.L2 [%0];" :: "l"(p));
}
// pack: low half = lo, high half = hi
__device__ __forceinline__ uint32_t cvt2(float lo, float hi) {
    uint32_t r; asm("cvt.rn.bf16x2.f32 %0, %1, %2;" : "=r"(r) : "f"(hi), "f"(lo)); return r;
}
__device__ __forceinline__ float lo16f(uint32_t u) { return __uint_as_float(u << 16); }
__device__ __forceinline__ float hi16f(uint32_t u) { return __uint_as_float(u & 0xffff0000u); }

__device__ __forceinline__ void ldsm4(uint32_t a, uint32_t& r0, uint32_t& r1,
                                      uint32_t& r2, uint32_t& r3) {
    asm volatile("ldmatrix.sync.aligned.m8n8.x4.shared.b16 {%0,%1,%2,%3}, [%4];"
                 : "=r"(r0), "=r"(r1), "=r"(r2), "=r"(r3) : "r"(a) : "memory");
}
__device__ __forceinline__ void mma16816(float* d, const uint32_t* a,
                                         uint32_t b0, uint32_t b1) {
    asm volatile(
        "mma.sync.aligned.m16n8k16.row.col.f32.bf16.bf16.f32 "
        "{%0,%1,%2,%3}, {%4,%5,%6,%7}, {%8,%9}, {%0,%1,%2,%3};"
        : "+f"(d[0]), "+f"(d[1]), "+f"(d[2]), "+f"(d[3])
        : "r"(a[0]), "r"(a[1]), "r"(a[2]), "r"(a[3]), "r"(b0), "r"(b1));
}

// Convert one 64x64 fp32 W level into swizzled bf16 hi/lo smem images (256 thr).
__device__ __forceinline__ void conv_B(const float* __restrict__ Wk,
                                       char* dst_hi, char* dst_lo, int tid) {
    const int o = tid >> 2, i0 = (tid & 3) * 16;
    const float4* wr = (const float4*)(Wk + o * 64 + i0);
    uint32_t h[8], l[8];
    #pragma unroll
    for (int u = 0; u < 4; ++u) {
        float4 q = wr[u];
        uint32_t h0 = cvt2(q.x, q.y);
        uint32_t h1 = cvt2(q.z, q.w);
        h[u * 2 + 0] = h0;
        h[u * 2 + 1] = h1;
        l[u * 2 + 0] = cvt2(q.x - lo16f(h0), q.y - hi16f(h0));
        l[u * 2 + 1] = cvt2(q.z - lo16f(h1), q.w - hi16f(h1));
    }
    uint32_t off0 = SW128((uint32_t)(o * 128 + i0 * 2));
    uint32_t off1 = SW128((uint32_t)(o * 128 + i0 * 2 + 16));
    *(uint4*)(dst_hi + off0) = make_uint4(h[0], h[1], h[2], h[3]);
    *(uint4*)(dst_hi + off1) = make_uint4(h[4], h[5], h[6], h[7]);
    *(uint4*)(dst_lo + off0) = make_uint4(l[0], l[1], l[2], l[3]);
    *(uint4*)(dst_lo + off1) = make_uint4(l[4], l[5], l[6], l[7]);
}

// ---------------------------------------------------------------------------
// Stage 16 X rows into this warp's smem seg as swizzled bf16 hi/lo via
// coalesced LDG.128, then ldmatrix the A fragments for all 4 k-chunks.
// ---------------------------------------------------------------------------
__device__ __forceinline__ void stage_A_frags(
    const float* __restrict__ Xrow, char* segp, uint32_t sseg, int lane,
    uint32_t ah[4][4], uint32_t al[4][4])
{
    const int r = lane >> 4;
    const int c4 = lane & 15;
    float4 q[8];
    #pragma unroll
    for (int i = 0; i < 8; ++i)
        q[i] = *(const float4*)(Xrow + (size_t)(i * 2 + r) * F + c4 * 4);

    __syncwarp();
    #pragma unroll
    for (int i = 0; i < 8; ++i) {
        uint32_t h0 = cvt2(q[i].x, q[i].y);
        uint32_t h1 = cvt2(q[i].z, q[i].w);
        uint32_t l0 = cvt2(q[i].x - lo16f(h0), q[i].y - hi16f(h0));
        uint32_t l1 = cvt2(q[i].z - lo16f(h1), q[i].w - hi16f(h1));
        uint32_t off = SW128((uint32_t)((i * 2 + r) * 128 + c4 * 8));
        *(ull*)(segp + off)        = (ull)h0 | ((ull)h1 << 32);
        *(ull*)(segp + 2176 + off) = (ull)l0 | ((ull)l1 << 32);
    }
    __syncwarp();

    const int arow = ((lane >> 3) & 1) * 8 + (lane & 7);
    const int acho = (lane >> 4) & 1;
    #pragma unroll
    for (int s = 0; s < 4; ++s) {
        uint32_t off = SW128((uint32_t)(arow * 128 + (2 * s + acho) * 16));
        ldsm4(sseg + off,        ah[s][0], ah[s][1], ah[s][2], ah[s][3]);
        ldsm4(sseg + 2176 + off, al[s][0], al[s][1], al[s][2], al[s][3]);
    }
    __syncwarp();
}

// MMA from prebuilt A fragments against B images (hi/lo), 3-product split.
__device__ __forceinline__ void mma_from_frags(
    const uint32_t ah[4][4], const uint32_t al[4][4],
    uint32_t sb_hi, uint32_t sb_lo, int lane, float D[8][4])
{
    const int brow = ((lane >> 4) & 1) * 8 + (lane & 7);
    const int bcho = (lane >> 3) & 1;

    #pragma unroll
    for (int nt = 0; nt < 8; ++nt)
        #pragma unroll
        for (int rr = 0; rr < 4; ++rr) D[nt][rr] = 0.f;

    #pragma unroll
    for (int s = 0; s < 4; ++s) {
        #pragma unroll
        for (int np = 0; np < 4; ++np) {
            uint32_t boff = SW128((uint32_t)((np * 16 + brow) * 128 + (2 * s + bcho) * 16));
            uint32_t bh[4], bl[4];
            ldsm4(sb_hi + boff, bh[0], bh[1], bh[2], bh[3]);
            ldsm4(sb_lo + boff, bl[0], bl[1], bl[2], bl[3]);
            mma16816(D[np * 2 + 0], ah[s], bh[0], bh[1]);
            mma16816(D[np * 2 + 0], al[s], bh[0], bh[1]);
            mma16816(D[np * 2 + 0], ah[s], bl[0], bl[1]);
            mma16816(D[np * 2 + 1], ah[s], bh[2], bh[3]);
            mma16816(D[np * 2 + 1], al[s], bh[2], bh[3]);
            mma16816(D[np * 2 + 1], ah[s], bl[2], bl[3]);
        }
    }
}

// Store a warp's 16-row D tile into its stage seg (fp32, pitch P floats).
__device__ __forceinline__ void stage_D(float* seg, const float D[8][4],
                                        int lane, const float* bias /*or null*/)
{
    const int gg = lane >> 2, t2 = (lane & 3) * 2;
    #pragma unroll
    for (int ntl = 0; ntl < 8; ++ntl) {
        const int c = ntl * 8 + t2;
        float b0 = bias ? bias[c] : 0.f, b1 = bias ? bias[c + 1] : 0.f;
        *(float2*)(seg + gg * P + c)       = make_float2(D[ntl][0] + b0, D[ntl][1] + b1);
        *(float2*)(seg + (gg + 8) * P + c) = make_float2(D[ntl][2] + b0, D[ntl][3] + b1);
    }
}

// ---------------------------------------------------------------------------
// Y producer (persistent): CTAs [0,296) HMMA tiles k=3..7 (992 jobs, balanced);
// CTAs [296,328): one CTA per batch, levels 8..14 via HMMA (k=8,9,10) +
// scalar tail (k=11..14, 15 rows) in warp 7.
// ---------------------------------------------------------------------------
__global__ __launch_bounds__(256, 2) void heap_mm_Y(
    const float* __restrict__ X, const float* __restrict__ W,
    const float* __restrict__ Bv)
{
    extern __shared__ char dsm[];
    const int tid = threadIdx.x;
    const int lane = tid & 31, warp = tid >> 5;
    const uint32_t sbase = smem_u32(dsm);

    if (blockIdx.x < YGRID_HMMA) {
        char* segp = dsm + YSTG + warp * SEG;
        const uint32_t sseg = sbase + YSTG + warp * SEG;
        const int J = 31 * 32;
        const int e0 = (int)(((long long)blockIdx.x * J) / YGRID_HMMA);
        const int e1 = (int)(((long long)(blockIdx.x + 1) * J) / YGRID_HMMA);

        if (e0 < e1) {
            const int b = e0 & 31;
            int rem = e0 >> 5, k = 3, nt = 16;
            while (rem >= nt) { rem -= nt; nt >>= 1; ++k; }
            pfL2(X + ((size_t)b * NODES + rem * 128 + warp * 16 + (lane >> 1)) * F
                   + (lane & 1) * 32);
        }

        int prevk = -1;
        for (int e = e0; e < e1; ++e) {
            const int b = e & 31;
            int rem = e >> 5, k = 3, nt = 16;
            while (rem >= nt) { rem -= nt; nt >>= 1; ++k; }
            const int a0 = rem * 128;

            if (k != prevk) {
                __syncthreads();
                conv_B(W + (size_t)k * F * F, dsm + YB_HI, dsm + YB_LO, tid);
                __syncthreads();
                prevk = k;
            }

            uint32_t ah[4][4], al[4][4];
            stage_A_frags(X + ((size_t)b * NODES + a0 + warp * 16) * F,
                          segp, sseg, lane, ah, al);
            float D[8][4];
            mma_from_frags(ah, al, sbase + YB_HI, sbase + YB_LO, lane, D);

            if (e + 1 < e1) {
                const int bn = (e + 1) & 31;
                int remn = (e + 1) >> 5, kn = 3, ntn = 16;
                while (remn >= ntn) { remn -= ntn; ntn >>= 1; ++kn; }
                const int a0n = remn * 128;
                pfL2(X + ((size_t)bn * NODES + a0n + warp * 16 + (lane >> 1)) * F
                       + (lane & 1) * 32);
            }

            float* seg = (float*)segp;
            stage_D(seg, D, lane, nullptr);
            __syncwarp();

            const int c4 = lane & 15;
            float4 bq = *(const float4*)(Bv + k * F + c4 * 4);
            float* yg = g_Y + YOFF(k) * (BATCH * F) + ((size_t)b * (NODES >> k)) * F;
            #pragma unroll
            for (int it = 0; it < 8; ++it) {
                const int rr = it * 2 + (lane >> 4);
                float4 v = *(const float4*)(seg + rr * P + c4 * 4);
                v.x += bq.x; v.y += bq.y; v.z += bq.z; v.w += bq.w;
                *(float4*)(yg + (size_t)(a0 + warp * 16 + rr) * F + c4 * 4) = v;
            }
            __syncwarp();
        }
    } else {
        // ---- small levels: CTA = batch ----
        const int b = blockIdx.x - YGRID_HMMA;        // 0..31 = batch

        if (tid < 128)
            pfL2(X + (size_t)b * NODES * F + tid * 32);

        conv_B(W + (size_t)8  * F * F, dsm + 0,     dsm + 8192,  tid);
        conv_B(W + (size_t)9  * F * F, dsm + 16384, dsm + 24576, tid);
        conv_B(W + (size_t)10 * F * F, dsm + 32768, dsm + 40960, tid);
        __syncthreads();

        if (warp < 7) {
            int k, r0w;
            if (warp < 4)      { k = 8;  r0w = warp * 16; }
            else if (warp < 6) { k = 9;  r0w = (warp - 4) * 16; }
            else               { k = 10; r0w = 0; }
            const uint32_t bimg = sbase + (uint32_t)(k - 8) * 16384;
            char* segp = dsm + 49152 + warp * SEG;
            const uint32_t sseg = sbase + 49152 + warp * SEG;

            uint32_t ah[4][4], al[4][4];
            stage_A_frags(X + ((size_t)b * NODES + r0w) * F, segp, sseg, lane, ah, al);
            float D[8][4];
            mma_from_frags(ah, al, bimg, bimg + 8192, lane, D);

            float* seg = (float*)segp;
            stage_D(seg, D, lane, nullptr);
            __syncwarp();

            const int c4 = lane & 15;
            float4 bq = *(const float4*)(Bv + k * F + c4 * 4);
            float* yg = g_Y + YOFF(k) * (BATCH * F)
                            + ((size_t)b * (NODES >> k) + r0w) * F;
            #pragma unroll
            for (int it = 0; it < 8; ++it) {
                const int rr = it * 2 + (lane >> 4);
                float4 v = *(const float4*)(seg + rr * P + c4 * 4);
                v.x += bq.x; v.y += bq.y; v.z += bq.z; v.w += bq.w;
                *(float4*)(yg + (size_t)rr * F + c4 * 4) = v;
            }
        } else {
            // scalar tail: k=11..14, rows (k,a): 8+4+2+1 = 15 rows.
            // Stage X rows 0..14 (960 consecutive floats) into warp 7's seg.
            float* xs = (float*)(dsm + 49152 + 7 * SEG);   // 3840B <= 4352
            const float* Xb0 = X + (size_t)b * NODES * F;
            for (int i = lane; i < 960; i += 32) xs[i] = Xb0[i];
            __syncwarp();

            for (int idx = lane; idx < 960; idx += 32) {
                const int i = idx >> 6, o = idx & 63;
                int k, a;
                if (i < 8)       { k = 11; a = i; }
                else if (i < 12) { k = 12; a = i - 8; }
                else if (i < 14) { k = 13; a = i - 12; }
                else             { k = 14; a = 0; }
                const float* xr = xs + a * 64;
                const float* wr = W + ((size_t)k * 64 + o) * 64;
                float s0 = 0.f, s1 = 0.f, s2 = 0.f, s3 = 0.f;
                #pragma unroll
                for (int i2 = 0; i2 < 64; i2 += 4) {
                    s0 = fmaf(xr[i2 + 0], __ldg(wr + i2 + 0), s0);
                    s1 = fmaf(xr[i2 + 1], __ldg(wr + i2 + 1), s1);
                    s2 = fmaf(xr[i2 + 2], __ldg(wr + i2 + 2), s2);
                    s3 = fmaf(xr[i2 + 3], __ldg(wr + i2 + 3), s3);
                }
                g_Y[YOFF(k) * (BATCH * F)
                    + ((size_t)b * (NODES >> k) + a) * F + o] =
                    Bv[k * F + o] + ((s0 + s1) + (s2 + s3));
            }
        }
    }
}

// ---------------------------------------------------------------------------
// Final (persistent, Y1+Y2 fused, G3 gather, staged I/O, L2 prefetch pipeline):
//   warps 0-3: Y1s = X[p0..] @ W1^T + b1 ; warps 4-5: Y2s = X[q0..] @ W2^T + b2
//   warps 6-7: G3s[r] = sum Y_{kp+3}[r>>kp]
//   all: D0 = X[a0..] @ W0^T -> stage -> coalesced merge (+b0 +Y1s +Y2s +G3s)
// ---------------------------------------------------------------------------
__global__ __launch_bounds__(256, 2) void heap_mm_final(
    const float* __restrict__ X, const float* __restrict__ W,
    const float* __restrict__ Bv, float* __restrict__ out)
{
    extern __shared__ char dsm[];
    const int tid = threadIdx.x;
    const int lane = tid & 31, warp = tid >> 5;
    const uint32_t sbase = smem_u32(dsm);
    char* segp = dsm + FSTG + warp * SEG;
    const uint32_t sseg = sbase + FSTG + warp * SEG;
    float* Y1s = (float*)(dsm + FY1S);
    float* Y2s = (float*)(dsm + FY2S);
    float* G3s = (float*)(dsm + FG3S);
    float* stage = (float*)(dsm + FSTG);     // 128 rows x P floats

    conv_B(W,        dsm + FB0HI, dsm + FB0LO, tid);
    conv_B(W + 4096, dsm + FB1HI, dsm + FB1LO, tid);
    conv_B(W + 8192, dsm + FB2HI, dsm + FB2LO, tid);

    const int J = 128 * 32, CH = (J + FGRID - 1) / FGRID;   // 14
    const int e0 = blockIdx.x * CH;
    const int e1 = min(e0 + CH, J);

    const int c4 = tid & 15;
    const float4 b0q = *(const float4*)(Bv + c4 * 4);
    const int pr = lane >> 1, ph = (lane & 1) * 32;   // prefetch row/half

    // warm L2 for the first job (main + role rows)
    {
        const int b = e0 >> 7, a0 = (e0 & 127) * 128;
        pfL2(X + ((size_t)b * NODES + a0 + warp * 16 + pr) * F + ph);
        if (warp < 4)
            pfL2(X + ((size_t)b * NODES + (a0 >> 1) + warp * 16 + pr) * F + ph);
        else if (warp < 6)
            pfL2(X + ((size_t)b * NODES + (a0 >> 2) + (warp - 4) * 16 + pr) * F + ph);
    }

    for (int e = e0; e < e1; ++e) {
        const int b = e >> 7;
        const int a0 = (e & 127) * 128;
        const int p0 = a0 >> 1, q0 = a0 >> 2, r0 = a0 >> 3;

        __syncthreads();   // stage/Y1s/Y2s/G3s free; B images ready

        if (warp < 4) {
            uint32_t ah[4][4], al[4][4];
            stage_A_frags(X + ((size_t)b * NODES + p0 + warp * 16) * F,
                          segp, sseg, lane, ah, al);
            float D1[8][4];
            mma_from_frags(ah, al, sbase + FB1HI, sbase + FB1LO, lane, D1);
            stage_D(Y1s + warp * 16 * P, D1, lane, Bv + F);
        } else if (warp < 6) {
            uint32_t ah[4][4], al[4][4];
            stage_A_frags(X + ((size_t)b * NODES + q0 + (warp - 4) * 16) * F,
                          segp, sseg, lane, ah, al);
            float D2[8][4];
            mma_from_frags(ah, al, sbase + FB2HI, sbase + FB2LO, lane, D2);
            stage_D(Y2s + (warp - 4) * 16 * P, D2, lane, Bv + 2 * F);
        } else {
            const int t3 = tid - 192;
            const int rl = t3 >> 2;
            const int r = r0 + rl;
            const int fq = (t3 & 3) * 16;
            const int level = r ? (32 - __clz((unsigned)r)) : 0;
            float4 a0v = make_float4(0.f, 0.f, 0.f, 0.f);
            float4 a1v = a0v, a2v = a0v, a3v = a0v;
            #pragma unroll
            for (int kp = 0; kp < 12; ++kp) {
                if (level >= kp) {
                    const int kk = kp + 3;
                    const float4* src = (const float4*)(
                        g_Y + YOFF(kk) * (BATCH * F)
                            + ((size_t)b * (NODES >> kk) + (r >> kp)) * F + fq);
                    float4 s0 = src[0], s1 = src[1], s2 = src[2], s3 = src[3];
                    a0v.x += s0.x; a0v.y += s0.y; a0v.z += s0.z; a0v.w += s0.w;
                    a1v.x += s1.x; a1v.y += s1.y; a1v.z += s1.z; a1v.w += s1.w;
                    a2v.x += s2.x; a2v.y += s2.y; a2v.z += s2.z; a2v.w += s2.w;
                    a3v.x += s3.x; a3v.y += s3.y; a3v.z += s3.z; a3v.w += s3.w;
                }
            }
            float4* gd = (float4*)(G3s + rl * P + fq);
            gd[0] = a0v; gd[1] = a1v; gd[2] = a2v; gd[3] = a3v;
        }

        // ---- main tile W0 (all warps; rows were L2-prefetched) ----
        {
            uint32_t ah[4][4], al[4][4];
            stage_A_frags(X + ((size_t)b * NODES + a0 + warp * 16) * F,
                          segp, sseg, lane, ah, al);
            float D0[8][4];
            mma_from_frags(ah, al, sbase + FB0HI, sbase + FB0LO, lane, D0);
            stage_D(stage + warp * 16 * P, D0, lane, nullptr);
        }

        // prefetch next job's main + role rows + G3 gather rows into L2
        if (e + 1 < e1) {
            const int bn = (e + 1) >> 7;
            const int a0n = ((e + 1) & 127) * 128;
            pfL2(X + ((size_t)bn * NODES + a0n + warp * 16 + pr) * F + ph);
            if (warp < 4) {
                pfL2(X + ((size_t)bn * NODES + (a0n >> 1) + warp * 16 + pr) * F + ph);
            } else if (warp < 6) {
                pfL2(X + ((size_t)bn * NODES + (a0n >> 2) + (warp - 4) * 16 + pr) * F + ph);
            } else {
                // G3 rows for next job, levels 3..6 (DRAM-resident part)
                const int t3 = tid - 192;
                const int rln = t3 >> 2;
                const int rn = (a0n >> 3) + rln;
                const int fqn = (t3 & 3) * 16;
                #pragma unroll
                for (int kp = 0; kp < 4; ++kp) {
                    const int kk = kp + 3;
                    pfL2(g_Y + YOFF(kk) * (BATCH * F)
                             + ((size_t)bn * (NODES >> kk) + (rn >> kp)) * F + fqn);
                }
            }
        }
        __syncthreads();   // all stage buffers complete

        // ---- coalesced merge + store ----
        float* ob = out + ((size_t)b * NODES + a0) * F;
        #pragma unroll
        for (int it = 0; it < 8; ++it) {
            const int row = it * 16 + (tid >> 4);
            const int j = a0 + row;
            float4 v = *(const float4*)(stage + row * P + c4 * 4);
            v.x += b0q.x; v.y += b0q.y; v.z += b0q.z; v.w += b0q.w;
            if (j >= 1) {
                float4 y1 = *(const float4*)(Y1s + (row >> 1) * P + c4 * 4);
                v.x += y1.x; v.y += y1.y; v.z += y1.z; v.w += y1.w;
            }
            if (j >= 2) {
                float4 y2 = *(const float4*)(Y2s + (row >> 2) * P + c4 * 4);
                v.x += y2.x; v.y += y2.y; v.z += y2.z; v.w += y2.w;
            }
            if (j >= 4) {
                float4 g3 = *(const float4*)(G3s + (row >> 3) * P + c4 * 4);
                v.x += g3.x; v.y += g3.y; v.z += g3.z; v.w += g3.w;
            }
            *(float4*)(ob + (size_t)row * F + c4 * 4) = v;
        }
    }
}

// ---------------------------------------------------------------------------
extern "C" void kernel_launch(void* const* d_in, const int* in_sizes, int n_in,
                              void* d_out, int out_size) {
    const float* X  = (const float*)d_in[0];   // [32, 16384, 64]
    const float* W  = (const float*)d_in[1];   // [15, 64, 64]
    const float* Bv = (const float*)d_in[2];   // [15, 64]
    float* out = (float*)d_out;                // [32, 16384, 64]

    cudaFuncSetAttribute(heap_mm_Y,
                         cudaFuncAttributeMaxDynamicSharedMemorySize, SMY_TOTAL);
    cudaFuncSetAttribute(heap_mm_final,
                         cudaFuncAttributeMaxDynamicSharedMemorySize, SMF_TOTAL);

    heap_mm_Y     <<<YGRID, 256, SMY_TOTAL>>>(X, W, Bv);
    heap_mm_final <<<FGRID, 256, SMF_TOTAL>>>(X, W, Bv, out);
}

// round 17
// speedup vs baseline: 1.2368x; 1.0745x over previous
#include <cuda_runtime.h>
#include <cuda_bf16.h>
#include <cstdint>

#define NODES 16384
#define BATCH 32
#define F 64

typedef unsigned long long ull;

// Y_k for k=3..14 (level k starts at row YOFF(k); k<3 unused).
__device__ float g_Y[(size_t)16383 * BATCH * F];
__device__ int g_done;   // CTAs that finished Y phase (reset each launch via ack)
__device__ int g_ack;    // CTAs that passed the wait

__host__ __device__ constexpr size_t YOFF(int k) {   // k >= 1
    return (size_t)(16384 - (16384 >> (k - 1)));
}

#define SW128(x) ((x) ^ (((x) >> 3) & 0x70))

// ---- dynamic smem layout (bytes) ----
#define FB0HI 0
#define FB0LO 8192
#define FB1HI 16384
#define FB1LO 24576
#define FB2HI 32768
#define FB2LO 40960
#define FSTG  49152                 // stage region: 8 segs x 4352 = 34816
#define SEG   4352                  // per-warp seg: A hi @0 (2KB), A lo @2176 (2KB)
#define FY1S  (FSTG + 8 * SEG)      // 83968: 64 x 68 fp32
#define FY2S  (FY1S + 17408)        // 32 x 68 fp32
#define FG3S  (FY2S + 8704)         // 16 x 68 fp32
#define SMF_TOTAL (FG3S + 4352)     // 114432
#define P 68                        // stage pitch in floats (272 B)

#define GRID  296                   // exactly 2 CTAs/SM x 148 SMs (residency!)
#define NCTA1 264                   // phase-1 HMMA CTAs; [264,296) = small levels

// ---------------- helpers ----------------
__device__ __forceinline__ uint32_t smem_u32(const void* p) {
    uint32_t a;
    asm("{ .reg .u64 t; cvta.to.shared.u64 t, %1; cvt.u32.u64 %0, t; }" : "=r"(a) : "l"(p));
    return a;
}
__device__ __forceinline__ void pfL2(const void* p) {
    asm volatile("prefetch.global.L2 [%0];" :: "l"(p));
}
// pack: low half = lo, high half = hi
__device__ __forceinline__ uint32_t cvt2(float lo, float hi) {
    uint32_t r; asm("cvt.rn.bf16x2.f32 %0, %1, %2;" : "=r"(r) : "f"(hi), "f"(lo)); return r;
}
__device__ __forceinline__ float lo16f(uint32_t u) { return __uint_as_float(u << 16); }
__device__ __forceinline__ float hi16f(uint32_t u) { return __uint_as_float(u & 0xffff0000u); }

__device__ __forceinline__ void ldsm4(uint32_t a, uint32_t& r0, uint32_t& r1,
                                      uint32_t& r2, uint32_t& r3) {
    asm volatile("ldmatrix.sync.aligned.m8n8.x4.shared.b16 {%0,%1,%2,%3}, [%4];"
                 : "=r"(r0), "=r"(r1), "=r"(r2), "=r"(r3) : "r"(a) : "memory");
}
__device__ __forceinline__ void mma16816(float* d, const uint32_t* a,
                                         uint32_t b0, uint32_t b1) {
    asm volatile(
        "mma.sync.aligned.m16n8k16.row.col.f32.bf16.bf16.f32 "
        "{%0,%1,%2,%3}, {%4,%5,%6,%7}, {%8,%9}, {%0,%1,%2,%3};"
        : "+f"(d[0]), "+f"(d[1]), "+f"(d[2]), "+f"(d[3])
        : "r"(a[0]), "r"(a[1]), "r"(a[2]), "r"(a[3]), "r"(b0), "r"(b1));
}

// Convert one 64x64 fp32 W level into swizzled bf16 hi/lo smem images (256 thr).
__device__ __forceinline__ void conv_B(const float* __restrict__ Wk,
                                       char* dst_hi, char* dst_lo, int tid) {
    const int o = tid >> 2, i0 = (tid & 3) * 16;
    const float4* wr = (const float4*)(Wk + o * 64 + i0);
    uint32_t h[8], l[8];
    #pragma unroll
    for (int u = 0; u < 4; ++u) {
        float4 q = wr[u];
        uint32_t h0 = cvt2(q.x, q.y);
        uint32_t h1 = cvt2(q.z, q.w);
        h[u * 2 + 0] = h0;
        h[u * 2 + 1] = h1;
        l[u * 2 + 0] = cvt2(q.x - lo16f(h0), q.y - hi16f(h0));
        l[u * 2 + 1] = cvt2(q.z - lo16f(h1), q.w - hi16f(h1));
    }
    uint32_t off0 = SW128((uint32_t)(o * 128 + i0 * 2));
    uint32_t off1 = SW128((uint32_t)(o * 128 + i0 * 2 + 16));
    *(uint4*)(dst_hi + off0) = make_uint4(h[0], h[1], h[2], h[3]);
    *(uint4*)(dst_hi + off1) = make_uint4(h[4], h[5], h[6], h[7]);
    *(uint4*)(dst_lo + off0) = make_uint4(l[0], l[1], l[2], l[3]);
    *(uint4*)(dst_lo + off1) = make_uint4(l[4], l[5], l[6], l[7]);
}

// ---------------------------------------------------------------------------
// Stage 16 X rows into a warp's smem seg as swizzled bf16 hi/lo via coalesced
// LDG.128, then ldmatrix the A fragments for all 4 k-chunks.
// ---------------------------------------------------------------------------
__device__ __forceinline__ void stage_A_frags(
    const float* __restrict__ Xrow, char* segp, uint32_t sseg, int lane,
    uint32_t ah[4][4], uint32_t al[4][4])
{
    const int r = lane >> 4;
    const int c4 = lane & 15;
    float4 q[8];
    #pragma unroll
    for (int i = 0; i < 8; ++i)
        q[i] = *(const float4*)(Xrow + (size_t)(i * 2 + r) * F + c4 * 4);

    __syncwarp();
    #pragma unroll
    for (int i = 0; i < 8; ++i) {
        uint32_t h0 = cvt2(q[i].x, q[i].y);
        uint32_t h1 = cvt2(q[i].z, q[i].w);
        uint32_t l0 = cvt2(q[i].x - lo16f(h0), q[i].y - hi16f(h0));
        uint32_t l1 = cvt2(q[i].z - lo16f(h1), q[i].w - hi16f(h1));
        uint32_t off = SW128((uint32_t)((i * 2 + r) * 128 + c4 * 8));
        *(ull*)(segp + off)        = (ull)h0 | ((ull)h1 << 32);
        *(ull*)(segp + 2176 + off) = (ull)l0 | ((ull)l1 << 32);
    }
    __syncwarp();

    const int arow = ((lane >> 3) & 1) * 8 + (lane & 7);
    const int acho = (lane >> 4) & 1;
    #pragma unroll
    for (int s = 0; s < 4; ++s) {
        uint32_t off = SW128((uint32_t)(arow * 128 + (2 * s + acho) * 16));
        ldsm4(sseg + off,        ah[s][0], ah[s][1], ah[s][2], ah[s][3]);
        ldsm4(sseg + 2176 + off, al[s][0], al[s][1], al[s][2], al[s][3]);
    }
    __syncwarp();
}

// MMA from prebuilt A fragments against B images (hi/lo), 3-product split.
__device__ __forceinline__ void mma_from_frags(
    const uint32_t ah[4][4], const uint32_t al[4][4],
    uint32_t sb_hi, uint32_t sb_lo, int lane, float D[8][4])
{
    const int brow = ((lane >> 4) & 1) * 8 + (lane & 7);
    const int bcho = (lane >> 3) & 1;

    #pragma unroll
    for (int nt = 0; nt < 8; ++nt)
        #pragma unroll
        for (int rr = 0; rr < 4; ++rr) D[nt][rr] = 0.f;

    #pragma unroll
    for (int s = 0; s < 4; ++s) {
        #pragma unroll
        for (int np = 0; np < 4; ++np) {
            uint32_t boff = SW128((uint32_t)((np * 16 + brow) * 128 + (2 * s + bcho) * 16));
            uint32_t bh[4], bl[4];
            ldsm4(sb_hi + boff, bh[0], bh[1], bh[2], bh[3]);
            ldsm4(sb_lo + boff, bl[0], bl[1], bl[2], bl[3]);
            mma16816(D[np * 2 + 0], ah[s], bh[0], bh[1]);
            mma16816(D[np * 2 + 0], al[s], bh[0], bh[1]);
            mma16816(D[np * 2 + 0], ah[s], bl[0], bl[1]);
            mma16816(D[np * 2 + 1], ah[s], bh[2], bh[3]);
            mma16816(D[np * 2 + 1], al[s], bh[2], bh[3]);
            mma16816(D[np * 2 + 1], ah[s], bl[2], bl[3]);
        }
    }
}

// Store a warp's 16-row D tile into a stage seg (fp32, pitch P floats).
__device__ __forceinline__ void stage_D(float* seg, const float D[8][4],
                                        int lane, const float* bias /*or null*/)
{
    const int gg = lane >> 2, t2 = (lane & 3) * 2;
    #pragma unroll
    for (int ntl = 0; ntl < 8; ++ntl) {
        const int c = ntl * 8 + t2;
        float b0 = bias ? bias[c] : 0.f, b1 = bias ? bias[c + 1] : 0.f;
        *(float2*)(seg + gg * P + c)       = make_float2(D[ntl][0] + b0, D[ntl][1] + b1);
        *(float2*)(seg + (gg + 8) * P + c) = make_float2(D[ntl][2] + b0, D[ntl][3] + b1);
    }
}

// ---------------------------------------------------------------------------
// FUSED kernel. Phase 1: produce g_Y (k=3..14). Phase 2: final jobs with
// Y1/Y2 fused + G3 gather (gated on g_done == GRID).
// ---------------------------------------------------------------------------
__global__ __launch_bounds__(256, 2) void heap_fused(
    const float* __restrict__ X, const float* __restrict__ W,
    const float* __restrict__ Bv, float* __restrict__ out)
{
    extern __shared__ char dsm[];
    const int tid = threadIdx.x;
    const int lane = tid & 31, warp = tid >> 5;
    const int bid = blockIdx.x;
    const uint32_t sbase = smem_u32(dsm);
    char* segp = dsm + FSTG + warp * SEG;
    const uint32_t sseg = sbase + FSTG + warp * SEG;
    float* Y1s = (float*)(dsm + FY1S);
    float* Y2s = (float*)(dsm + FY2S);
    float* G3s = (float*)(dsm + FG3S);
    float* stage = (float*)(dsm + FSTG);     // 128 rows x P floats

    // ===================== PHASE 1: Y production =====================
    if (bid < NCTA1) {
        const int J = 31 * 32;   // 992 HMMA jobs, k=3..7
        const int e0 = (int)(((long long)bid * J) / NCTA1);
        const int e1 = (int)(((long long)(bid + 1) * J) / NCTA1);

        if (e0 < e1) {
            const int b = e0 & 31;
            int rem = e0 >> 5, k = 3, nt = 16;
            while (rem >= nt) { rem -= nt; nt >>= 1; ++k; }
            pfL2(X + ((size_t)b * NODES + rem * 128 + warp * 16 + (lane >> 1)) * F
                   + (lane & 1) * 32);
        }

        int prevk = -1;
        for (int e = e0; e < e1; ++e) {
            const int b = e & 31;
            int rem = e >> 5, k = 3, nt = 16;
            while (rem >= nt) { rem -= nt; nt >>= 1; ++k; }
            const int a0 = rem * 128;

            if (k != prevk) {
                __syncthreads();
                conv_B(W + (size_t)k * F * F, dsm + FB0HI, dsm + FB0LO, tid);
                __syncthreads();
                prevk = k;
            }

            uint32_t ah[4][4], al[4][4];
            stage_A_frags(X + ((size_t)b * NODES + a0 + warp * 16) * F,
                          segp, sseg, lane, ah, al);
            float D[8][4];
            mma_from_frags(ah, al, sbase + FB0HI, sbase + FB0LO, lane, D);

            if (e + 1 < e1) {
                const int bn = (e + 1) & 31;
                int remn = (e + 1) >> 5, kn = 3, ntn = 16;
                while (remn >= ntn) { remn -= ntn; ntn >>= 1; ++kn; }
                const int a0n = remn * 128;
                pfL2(X + ((size_t)bn * NODES + a0n + warp * 16 + (lane >> 1)) * F
                       + (lane & 1) * 32);
            }

            float* seg = (float*)segp;
            stage_D(seg, D, lane, nullptr);
            __syncwarp();

            const int c4 = lane & 15;
            float4 bq = *(const float4*)(Bv + k * F + c4 * 4);
            float* yg = g_Y + YOFF(k) * (BATCH * F) + ((size_t)b * (NODES >> k)) * F;
            #pragma unroll
            for (int it = 0; it < 8; ++it) {
                const int rr = it * 2 + (lane >> 4);
                float4 v = *(const float4*)(seg + rr * P + c4 * 4);
                v.x += bq.x; v.y += bq.y; v.z += bq.z; v.w += bq.w;
                *(float4*)(yg + (size_t)(a0 + warp * 16 + rr) * F + c4 * 4) = v;
            }
            __syncwarp();
        }
    } else {
        // small levels, batch b = bid - NCTA1
        const int b = bid - NCTA1;

        if (tid < 128)
            pfL2(X + (size_t)b * NODES * F + tid * 32);

        conv_B(W + (size_t)8  * F * F, dsm + FB0HI, dsm + FB0LO, tid);
        conv_B(W + (size_t)9  * F * F, dsm + FB1HI, dsm + FB1LO, tid);
        conv_B(W + (size_t)10 * F * F, dsm + FB2HI, dsm + FB2LO, tid);
        __syncthreads();

        if (warp < 7) {
            int k, r0w;
            if (warp < 4)      { k = 8;  r0w = warp * 16; }
            else if (warp < 6) { k = 9;  r0w = (warp - 4) * 16; }
            else               { k = 10; r0w = 0; }
            const uint32_t bimg = sbase + (uint32_t)(k - 8) * 16384;

            uint32_t ah[4][4], al[4][4];
            stage_A_frags(X + ((size_t)b * NODES + r0w) * F, segp, sseg, lane, ah, al);
            float D[8][4];
            mma_from_frags(ah, al, bimg, bimg + 8192, lane, D);

            float* seg = (float*)segp;
            stage_D(seg, D, lane, nullptr);
            __syncwarp();

            const int c4 = lane & 15;
            float4 bq = *(const float4*)(Bv + k * F + c4 * 4);
            float* yg = g_Y + YOFF(k) * (BATCH * F)
                            + ((size_t)b * (NODES >> k) + r0w) * F;
            #pragma unroll
            for (int it = 0; it < 8; ++it) {
                const int rr = it * 2 + (lane >> 4);
                float4 v = *(const float4*)(seg + rr * P + c4 * 4);
                v.x += bq.x; v.y += bq.y; v.z += bq.z; v.w += bq.w;
                *(float4*)(yg + (size_t)rr * F + c4 * 4) = v;
            }
        } else {
            // scalar tail: k=11..14, 15 rows total; X rows 0..14 staged in seg
            float* xs = (float*)(dsm + FSTG + 7 * SEG);   // 3840B <= 4352
            const float* Xb0 = X + (size_t)b * NODES * F;
            for (int i = lane; i < 960; i += 32) xs[i] = Xb0[i];
            __syncwarp();

            for (int idx = lane; idx < 960; idx += 32) {
                const int i = idx >> 6, o = idx & 63;
                int k, a;
                if (i < 8)       { k = 11; a = i; }
                else if (i < 12) { k = 12; a = i - 8; }
                else if (i < 14) { k = 13; a = i - 12; }
                else             { k = 14; a = 0; }
                const float* xr = xs + a * 64;
                const float* wr = W + ((size_t)k * 64 + o) * 64;
                float s0 = 0.f, s1 = 0.f, s2 = 0.f, s3 = 0.f;
                #pragma unroll
                for (int i2 = 0; i2 < 64; i2 += 4) {
                    s0 = fmaf(xr[i2 + 0], __ldg(wr + i2 + 0), s0);
                    s1 = fmaf(xr[i2 + 1], __ldg(wr + i2 + 1), s1);
                    s2 = fmaf(xr[i2 + 2], __ldg(wr + i2 + 2), s2);
                    s3 = fmaf(xr[i2 + 3], __ldg(wr + i2 + 3), s3);
                }
                g_Y[YOFF(k) * (BATCH * F)
                    + ((size_t)b * (NODES >> k) + a) * F + o] =
                    Bv[k * F + o] + ((s0 + s1) + (s2 + s3));
            }
        }
    }

    // signal Y done (after ALL warps' stores)
    __syncthreads();
    if (tid == 0) {
        __threadfence();
        atomicAdd(&g_done, 1);
    }

    // convert W0/W1/W2 B images for phase 2 (overwrites phase-1 B areas)
    conv_B(W,        dsm + FB0HI, dsm + FB0LO, tid);
    conv_B(W + 4096, dsm + FB1HI, dsm + FB1LO, tid);
    conv_B(W + 8192, dsm + FB2HI, dsm + FB2LO, tid);

    // ===================== PHASE 2: final jobs =====================
    const int J2 = 128 * 32;
    const int f0 = (int)(((long long)bid * J2) / GRID);
    const int f1 = (int)(((long long)(bid + 1) * J2) / GRID);

    const int c4 = tid & 15;
    const float4 b0q = *(const float4*)(Bv + c4 * 4);
    const int pr = lane >> 1, ph = (lane & 1) * 32;
    bool g3_ready = false;

    // warm L2 for the first job
    {
        const int b = f0 >> 7, a0 = (f0 & 127) * 128;
        pfL2(X + ((size_t)b * NODES + a0 + warp * 16 + pr) * F + ph);
        if (warp < 4)
            pfL2(X + ((size_t)b * NODES + (a0 >> 1) + warp * 16 + pr) * F + ph);
        else if (warp < 6)
            pfL2(X + ((size_t)b * NODES + (a0 >> 2) + (warp - 4) * 16 + pr) * F + ph);
    }

    for (int e = f0; e < f1; ++e) {
        const int b = e >> 7;
        const int a0 = (e & 127) * 128;
        const int p0 = a0 >> 1, q0 = a0 >> 2, r0 = a0 >> 3;

        __syncthreads();   // stage buffers free; B images ready

        if (warp < 4) {
            uint32_t ah[4][4], al[4][4];
            stage_A_frags(X + ((size_t)b * NODES + p0 + warp * 16) * F,
                          segp, sseg, lane, ah, al);
            float D1[8][4];
            mma_from_frags(ah, al, sbase + FB1HI, sbase + FB1LO, lane, D1);
            stage_D(Y1s + warp * 16 * P, D1, lane, Bv + F);
        } else if (warp < 6) {
            uint32_t ah[4][4], al[4][4];
            stage_A_frags(X + ((size_t)b * NODES + q0 + (warp - 4) * 16) * F,
                          segp, sseg, lane, ah, al);
            float D2[8][4];
            mma_from_frags(ah, al, sbase + FB2HI, sbase + FB2LO, lane, D2);
            stage_D(Y2s + (warp - 4) * 16 * P, D2, lane, Bv + 2 * F);
        } else {
            // wait for ALL CTAs' Y phase before first gather
            if (!g3_ready) {
                if (lane == 0) {
                    volatile int* vd = &g_done;
                    while (*vd < GRID) __nanosleep(64);
                }
                __syncwarp();
                __threadfence();
                if (tid == 224) {
                    int old = atomicAdd(&g_ack, 1);
                    if (old == GRID - 1) {     // last: reset for next launch
                        *(volatile int*)&g_done = 0;
                        *(volatile int*)&g_ack  = 0;
                        __threadfence();
                    }
                }
                g3_ready = true;
            }
            const int t3 = tid - 192;
            const int rl = t3 >> 2;
            const int r = r0 + rl;
            const int fq = (t3 & 3) * 16;
            const int level = r ? (32 - __clz((unsigned)r)) : 0;
            float4 a0v = make_float4(0.f, 0.f, 0.f, 0.f);
            float4 a1v = a0v, a2v = a0v, a3v = a0v;
            #pragma unroll
            for (int kp = 0; kp < 12; ++kp) {
                if (level >= kp) {
                    const int kk = kp + 3;
                    const float4* src = (const float4*)(
                        g_Y + YOFF(kk) * (BATCH * F)
                            + ((size_t)b * (NODES >> kk) + (r >> kp)) * F + fq);
                    float4 s0 = src[0], s1 = src[1], s2 = src[2], s3 = src[3];
                    a0v.x += s0.x; a0v.y += s0.y; a0v.z += s0.z; a0v.w += s0.w;
                    a1v.x += s1.x; a1v.y += s1.y; a1v.z += s1.z; a1v.w += s1.w;
                    a2v.x += s2.x; a2v.y += s2.y; a2v.z += s2.z; a2v.w += s2.w;
                    a3v.x += s3.x; a3v.y += s3.y; a3v.z += s3.z; a3v.w += s3.w;
                }
            }
            float4* gd = (float4*)(G3s + rl * P + fq);
            gd[0] = a0v; gd[1] = a1v; gd[2] = a2v; gd[3] = a3v;
        }

        // ---- main tile W0 (all warps) ----
        {
            uint32_t ah[4][4], al[4][4];
            stage_A_frags(X + ((size_t)b * NODES + a0 + warp * 16) * F,
                          segp, sseg, lane, ah, al);
            float D0[8][4];
            mma_from_frags(ah, al, sbase + FB0HI, sbase + FB0LO, lane, D0);
            stage_D(stage + warp * 16 * P, D0, lane, nullptr);
        }

        // prefetch next job's main + role + G3 rows into L2
        if (e + 1 < f1) {
            const int bn = (e + 1) >> 7;
            const int a0n = ((e + 1) & 127) * 128;
            pfL2(X + ((size_t)bn * NODES + a0n + warp * 16 + pr) * F + ph);
            if (warp < 4) {
                pfL2(X + ((size_t)bn * NODES + (a0n >> 1) + warp * 16 + pr) * F + ph);
            } else if (warp < 6) {
                pfL2(X + ((size_t)bn * NODES + (a0n >> 2) + (warp - 4) * 16 + pr) * F + ph);
            } else {
                const int t3 = tid - 192;
                const int rln = t3 >> 2;
                const int rn = (a0n >> 3) + rln;
                const int fqn = (t3 & 3) * 16;
                #pragma unroll
                for (int kp = 0; kp < 4; ++kp) {
                    const int kk = kp + 3;
                    pfL2(g_Y + YOFF(kk) * (BATCH * F)
                             + ((size_t)bn * (NODES >> kk) + (rn >> kp)) * F + fqn);
                }
            }
        }
        __syncthreads();   // all stage buffers complete

        // ---- coalesced merge + store ----
        float* ob = out + ((size_t)b * NODES + a0) * F;
        #pragma unroll
        for (int it = 0; it < 8; ++it) {
            const int row = it * 16 + (tid >> 4);
            const int j = a0 + row;
            float4 v = *(const float4*)(stage + row * P + c4 * 4);
            v.x += b0q.x; v.y += b0q.y; v.z += b0q.z; v.w += b0q.w;
            if (j >= 1) {
                float4 y1 = *(const float4*)(Y1s + (row >> 1) * P + c4 * 4);
                v.x += y1.x; v.y += y1.y; v.z += y1.z; v.w += y1.w;
            }
            if (j >= 2) {
                float4 y2 = *(const float4*)(Y2s + (row >> 2) * P + c4 * 4);
                v.x += y2.x; v.y += y2.y; v.z += y2.z; v.w += y2.w;
            }
            if (j >= 4) {
                float4 g3 = *(const float4*)(G3s + (row >> 3) * P + c4 * 4);
                v.x += g3.x; v.y += g3.y; v.z += g3.z; v.w += g3.w;
            }
            *(float4*)(ob + (size_t)row * F + c4 * 4) = v;
        }
    }
}

// ---------------------------------------------------------------------------
extern "C" void kernel_launch(void* const* d_in, const int* in_sizes, int n_in,
                              void* d_out, int out_size) {
    const float* X  = (const float*)d_in[0];   // [32, 16384, 64]
    const float* W  = (const float*)d_in[1];   // [15, 64, 64]
    const float* Bv = (const float*)d_in[2];   // [15, 64]
    float* out = (float*)d_out;                // [32, 16384, 64]

    cudaFuncSetAttribute(heap_fused,
                         cudaFuncAttributeMaxDynamicSharedMemorySize, SMF_TOTAL);

    heap_fused<<<GRID, 256, SMF_TOTAL>>>(X, W, Bv, out);
}